// round 3
// baseline (speedup 1.0000x reference)
#include <cuda_runtime.h>
#include <math.h>

#define EMBED   768
#define THREE_E 2304
#define HEADS   12
#define HD      64
#define BATCH   8
#define SEQ     1024
#define M_TOTAL (BATCH * SEQ)          // 8192
#define PER_BUF ((size_t)BATCH * HEADS * SEQ * HD)   // 6,291,456 floats

// Scratch for Q/K/V in [which][b][h][n][d] layout (device global: no allocs allowed)
__device__ float g_qkv[3 * PER_BUF];

// ---------------------------------------------------------------------------
// Kernel 1: QKV projection.  out[m][c] = sum_k X[m][k]*W[c][k] + bias[c]
// 128x128 tile, BK=8, 256 threads, 8x8 microtile. Epilogue scatters into
// g_qkv[which][b][h][n][d]  (c -> h = c/192, r = c%192, which = r/64, d = r%64)
// ---------------------------------------------------------------------------
__global__ __launch_bounds__(256) void qkv_gemm_kernel(
    const float* __restrict__ X, const float* __restrict__ W,
    const float* __restrict__ bias)
{
    __shared__ float Xs[8][128];
    __shared__ float Ws[8][128];

    const int tid = threadIdx.x;
    const int m0 = blockIdx.y * 128;
    const int n0 = blockIdx.x * 128;
    const int tx = tid & 15;          // 0..15  (cols)
    const int ty = tid >> 4;          // 0..15  (rows)
    const int lrow = tid >> 1;        // 0..127
    const int lvec = (tid & 1) * 4;   // 0 or 4

    float acc[8][8];
#pragma unroll
    for (int i = 0; i < 8; i++)
#pragma unroll
        for (int j = 0; j < 8; j++) acc[i][j] = 0.f;

    const float* xptr = X + (size_t)(m0 + lrow) * EMBED + lvec;
    const float* wptr = W + (size_t)(n0 + lrow) * EMBED + lvec;

    for (int k0 = 0; k0 < EMBED; k0 += 8) {
        float4 xv = *(const float4*)(xptr + k0);
        float4 wv = *(const float4*)(wptr + k0);
        __syncthreads();
        Xs[lvec + 0][lrow] = xv.x; Xs[lvec + 1][lrow] = xv.y;
        Xs[lvec + 2][lrow] = xv.z; Xs[lvec + 3][lrow] = xv.w;
        Ws[lvec + 0][lrow] = wv.x; Ws[lvec + 1][lrow] = wv.y;
        Ws[lvec + 2][lrow] = wv.z; Ws[lvec + 3][lrow] = wv.w;
        __syncthreads();
#pragma unroll
        for (int k = 0; k < 8; k++) {
            float a[8], b[8];
            *(float4*)(a)     = *(const float4*)(&Xs[k][ty * 8]);
            *(float4*)(a + 4) = *(const float4*)(&Xs[k][ty * 8 + 4]);
            *(float4*)(b)     = *(const float4*)(&Ws[k][tx * 8]);
            *(float4*)(b + 4) = *(const float4*)(&Ws[k][tx * 8 + 4]);
#pragma unroll
            for (int i = 0; i < 8; i++)
#pragma unroll
                for (int j = 0; j < 8; j++)
                    acc[i][j] = fmaf(a[i], b[j], acc[i][j]);
        }
    }

    float bb[8];
#pragma unroll
    for (int j = 0; j < 8; j++) bb[j] = bias[n0 + tx * 8 + j];

#pragma unroll
    for (int i = 0; i < 8; i++) {
        int m = m0 + ty * 8 + i;
        int bidx = m >> 10;              // m / 1024
        int n    = m & (SEQ - 1);
#pragma unroll
        for (int j = 0; j < 8; j++) {
            int c = n0 + tx * 8 + j;
            int hh = c / 192;
            int r  = c - hh * 192;
            int which = r >> 6;
            int d = r & 63;
            size_t idx = ((((size_t)which * BATCH + bidx) * HEADS + hh) * SEQ + n) * HD + d;
            g_qkv[idx] = acc[i][j] + bb[j];
        }
    }
}

// ---------------------------------------------------------------------------
// Kernel 2: flash-style attention, fp32. One CTA = (b, h, 64 queries).
// 256 threads: 4 threads / query, each owns 16 output dims.
// K/V tiles of 64 keys staged in smem (stride 68 to keep float4 conflict-free).
// ---------------------------------------------------------------------------
#define STRD 68
#define ATTN_SMEM (4 * 64 * STRD * sizeof(float))   // 69632 B

__global__ __launch_bounds__(256) void attn_kernel(float* __restrict__ out)
{
    extern __shared__ float sm[];
    float* Qs = sm;                 // [64][STRD]
    float* Ks = Qs + 64 * STRD;
    float* Vs = Ks + 64 * STRD;
    float* Ss = Vs + 64 * STRD;

    const int b  = blockIdx.z;
    const int h  = blockIdx.y;
    const int m0 = blockIdx.x * 64;
    const size_t bh = ((size_t)b * HEADS + h) * SEQ * HD;
    const float* Qp = g_qkv + bh + (size_t)m0 * HD;
    const float* Kp = g_qkv + PER_BUF + bh;
    const float* Vp = g_qkv + 2 * PER_BUF + bh;

    const int tid = threadIdx.x;

    // stage Q tile (64x64)
    for (int i = tid; i < 64 * 16; i += 256) {
        int r = i >> 4, cv = (i & 15) * 4;
        *(float4*)(Qs + r * STRD + cv) = *(const float4*)(Qp + r * HD + cv);
    }

    const int q  = tid >> 2;           // 0..63
    const int ds = (tid & 3) * 16;     // dim slice base
    float acc[16];
#pragma unroll
    for (int d = 0; d < 16; d++) acc[d] = 0.f;
    float mrow = -1e30f, lrow = 0.f;

    for (int n0 = 0; n0 < SEQ; n0 += 64) {
        __syncthreads();   // previous-tile reads of Ks/Vs/Ss done (also covers Q stage)
        for (int i = tid; i < 64 * 16; i += 256) {
            int r = i >> 4, cv = (i & 15) * 4;
            *(float4*)(Ks + r * STRD + cv) = *(const float4*)(Kp + (size_t)(n0 + r) * HD + cv);
            *(float4*)(Vs + r * STRD + cv) = *(const float4*)(Vp + (size_t)(n0 + r) * HD + cv);
        }
        __syncthreads();

        // S[q][ds..ds+15] = Q[q] . K[j]
        float s[16];
#pragma unroll
        for (int jj = 0; jj < 16; jj++) s[jj] = 0.f;
#pragma unroll
        for (int kk = 0; kk < 64; kk += 4) {
            float4 qv = *(const float4*)(Qs + q * STRD + kk);
#pragma unroll
            for (int jj = 0; jj < 16; jj++) {
                float4 kv = *(const float4*)(Ks + (ds + jj) * STRD + kk);
                s[jj] = fmaf(qv.x, kv.x, s[jj]);
                s[jj] = fmaf(qv.y, kv.y, s[jj]);
                s[jj] = fmaf(qv.z, kv.z, s[jj]);
                s[jj] = fmaf(qv.w, kv.w, s[jj]);
            }
        }
#pragma unroll
        for (int jj = 0; jj < 16; jj++)
            Ss[q * STRD + ds + jj] = s[jj] * 0.125f;   // 1/sqrt(64)
        __syncthreads();

        // online softmax + PV accumulate (each quad-thread recomputes row stats)
        const float* srow = Ss + q * STRD;
        float mnew = mrow;
#pragma unroll
        for (int j = 0; j < 64; j++) mnew = fmaxf(mnew, srow[j]);
        float alpha = __expf(mrow - mnew);
#pragma unroll
        for (int d = 0; d < 16; d++) acc[d] *= alpha;
        float lsum = 0.f;
        for (int j = 0; j < 64; j++) {
            float p = __expf(srow[j] - mnew);
            lsum += p;
            const float* vrow = Vs + j * STRD + ds;
#pragma unroll
            for (int d = 0; d < 16; d += 4) {
                float4 vv = *(const float4*)(vrow + d);
                acc[d + 0] = fmaf(p, vv.x, acc[d + 0]);
                acc[d + 1] = fmaf(p, vv.y, acc[d + 1]);
                acc[d + 2] = fmaf(p, vv.z, acc[d + 2]);
                acc[d + 3] = fmaf(p, vv.w, acc[d + 3]);
            }
        }
        lrow = lrow * alpha + lsum;
        mrow = mnew;
    }

    float inv = 1.f / lrow;
    float* op = out + ((size_t)b * SEQ + m0 + q) * EMBED + h * HD + ds;
#pragma unroll
    for (int d = 0; d < 16; d++) op[d] = acc[d] * inv;
}

// ---------------------------------------------------------------------------
extern "C" void kernel_launch(void* const* d_in, const int* in_sizes, int n_in,
                              void* d_out, int out_size)
{
    const float* x    = (const float*)d_in[0];   // (8,1024,768)
    const float* W    = (const float*)d_in[1];   // (2304,768)
    const float* bias = (const float*)d_in[2];   // (2304,)
    float* out = (float*)d_out;                  // (8,1024,768)

    dim3 ggrid(THREE_E / 128, M_TOTAL / 128);    // (18, 64)
    qkv_gemm_kernel<<<ggrid, 256>>>(x, W, bias);

    cudaFuncSetAttribute(attn_kernel, cudaFuncAttributeMaxDynamicSharedMemorySize,
                         (int)ATTN_SMEM);
    dim3 agrid(SEQ / 64, HEADS, BATCH);          // (16, 12, 8)
    attn_kernel<<<agrid, 256, ATTN_SMEM>>>(out);
}

// round 4
// speedup vs baseline: 2.8157x; 2.8157x over previous
#include <cuda_runtime.h>
#include <math.h>

#define EMBED   768
#define THREE_E 2304
#define HEADS   12
#define HD      64
#define BATCH   8
#define SEQ     1024
#define M_TOTAL (BATCH * SEQ)          // 8192
#define PER_BUF ((size_t)BATCH * HEADS * SEQ * HD)   // 6,291,456 floats

typedef unsigned long long ull;

// Scratch for Q/K/V in [which][b][h][n][d] layout
__device__ float g_qkv[3 * PER_BUF];

// ---- packed f32x2 helpers (Blackwell-only; ptxas never auto-fuses these) ----
#define PACK2(d, x)    asm("mov.b64 %0, {%1, %1};" : "=l"(d) : "f"(x))
#define UNPK2(lo,hi,v) asm("mov.b64 {%0, %1}, %2;" : "=f"(lo), "=f"(hi) : "l"(v))
#define FMA2(d, a, b)  asm("fma.rn.f32x2 %0, %1, %2, %0;" : "+l"(d) : "l"(a), "l"(b))
#define MUL2(d, a, b)  asm("mul.rn.f32x2 %0, %1, %2;" : "=l"(d) : "l"(a), "l"(b))

// ---------------------------------------------------------------------------
// Kernel 1: QKV projection with f32x2 FMA.  out[m][c] = X[m]·W[c] + bias[c]
// 128x128 tile, BK=8, 256 threads, 8x8 microtile (rows packed in pairs).
// ---------------------------------------------------------------------------
__global__ __launch_bounds__(256) void qkv_gemm_kernel(
    const float* __restrict__ X, const float* __restrict__ W,
    const float* __restrict__ bias)
{
    __shared__ float Xs[8][128];
    __shared__ float Ws[8][128];

    const int tid = threadIdx.x;
    const int m0 = blockIdx.y * 128;
    const int n0 = blockIdx.x * 128;
    const int tx = tid & 15;          // 0..15  (cols)
    const int ty = tid >> 4;          // 0..15  (rows)
    const int lrow = tid >> 1;        // 0..127
    const int lvec = (tid & 1) * 4;   // 0 or 4

    ull acc2[4][8];                   // row-pairs x 8 cols
#pragma unroll
    for (int i = 0; i < 4; i++)
#pragma unroll
        for (int j = 0; j < 8; j++) acc2[i][j] = 0ULL;

    const float* xptr = X + (size_t)(m0 + lrow) * EMBED + lvec;
    const float* wptr = W + (size_t)(n0 + lrow) * EMBED + lvec;

    for (int k0 = 0; k0 < EMBED; k0 += 8) {
        float4 xv = *(const float4*)(xptr + k0);
        float4 wv = *(const float4*)(wptr + k0);
        __syncthreads();
        Xs[lvec + 0][lrow] = xv.x; Xs[lvec + 1][lrow] = xv.y;
        Xs[lvec + 2][lrow] = xv.z; Xs[lvec + 3][lrow] = xv.w;
        Ws[lvec + 0][lrow] = wv.x; Ws[lvec + 1][lrow] = wv.y;
        Ws[lvec + 2][lrow] = wv.z; Ws[lvec + 3][lrow] = wv.w;
        __syncthreads();
#pragma unroll
        for (int k = 0; k < 8; k++) {
            ulonglong2 xa = *(const ulonglong2*)(&Xs[k][ty * 8]);
            ulonglong2 xb = *(const ulonglong2*)(&Xs[k][ty * 8 + 4]);
            float4 w0 = *(const float4*)(&Ws[k][tx * 8]);
            float4 w1 = *(const float4*)(&Ws[k][tx * 8 + 4]);
            ull wd[8];
            PACK2(wd[0], w0.x); PACK2(wd[1], w0.y);
            PACK2(wd[2], w0.z); PACK2(wd[3], w0.w);
            PACK2(wd[4], w1.x); PACK2(wd[5], w1.y);
            PACK2(wd[6], w1.z); PACK2(wd[7], w1.w);
            ull xp[4] = {xa.x, xa.y, xb.x, xb.y};
#pragma unroll
            for (int ip = 0; ip < 4; ip++)
#pragma unroll
                for (int j = 0; j < 8; j++)
                    FMA2(acc2[ip][j], xp[ip], wd[j]);
        }
    }

    float bb[8];
#pragma unroll
    for (int j = 0; j < 8; j++) bb[j] = bias[n0 + tx * 8 + j];

#pragma unroll
    for (int ip = 0; ip < 4; ip++) {
#pragma unroll
        for (int j = 0; j < 8; j++) {
            float v0, v1;
            UNPK2(v0, v1, acc2[ip][j]);
            int c = n0 + tx * 8 + j;
            int hh = c / 192;
            int r  = c - hh * 192;
            int which = r >> 6;
            int d = r & 63;
#pragma unroll
            for (int dd = 0; dd < 2; dd++) {
                int m = m0 + ty * 8 + ip * 2 + dd;
                int bidx = m >> 10;
                int n    = m & (SEQ - 1);
                size_t idx = ((((size_t)which * BATCH + bidx) * HEADS + hh) * SEQ + n) * HD + d;
                g_qkv[idx] = (dd ? v1 : v0) + bb[j];
            }
        }
    }
}

// ---------------------------------------------------------------------------
// Kernel 2: flash attention, fp32 + f32x2 FMA, register-tiled.
// CTA = (b, h, 128 queries). 128 threads in 16(q-blocks) x 8(col-blocks).
// Octet (8 threads, same ty) shares 8 query rows; P exchanged via shfl.
// smem: Qt[64][128] (d-major, pre-scaled), Kt[64][64] (d-major), Vs[64][68].
// ---------------------------------------------------------------------------
#define ATTN_SMEM ((8192 + 4096 + 64*68) * sizeof(float))   // 66,560 B

__global__ __launch_bounds__(128) void attn_kernel(float* __restrict__ out)
{
    extern __shared__ float sm[];
    float* Qt = sm;             // [64][128]
    float* Kt = sm + 8192;      // [64][64]
    float* Vs = sm + 12288;     // [64][68]

    const int b  = blockIdx.z;
    const int h  = blockIdx.y;
    const int m0 = blockIdx.x * 128;
    const size_t bh = ((size_t)b * HEADS + h) * SEQ * HD;
    const float* Qp = g_qkv + bh + (size_t)m0 * HD;
    const float* Kp = g_qkv + PER_BUF + bh;
    const float* Vp = g_qkv + 2 * PER_BUF + bh;

    const int tid = threadIdx.x;
    const int tx  = tid & 7;          // col-block (keys in QK, dims in PV)
    const int ty  = tid >> 3;         // query-block
    const int q0  = ty * 8;
    const int c0  = tx * 8;

    // stage Qt transposed, pre-scaled by 1/sqrt(64); conflict-free STS (bank = n)
#pragma unroll
    for (int it = 0; it < 16; it++) {
        int dv = it * 4;
        float4 v = *(const float4*)(Qp + (size_t)tid * HD + dv);
        Qt[(dv + 0) * 128 + tid] = v.x * 0.125f;
        Qt[(dv + 1) * 128 + tid] = v.y * 0.125f;
        Qt[(dv + 2) * 128 + tid] = v.z * 0.125f;
        Qt[(dv + 3) * 128 + tid] = v.w * 0.125f;
    }

    ull o2[8][4];                    // 8 rows x 8 dims (packed pairs)
#pragma unroll
    for (int i = 0; i < 8; i++)
#pragma unroll
        for (int dp = 0; dp < 4; dp++) o2[i][dp] = 0ULL;
    float mrow[8], lrow[8];
#pragma unroll
    for (int i = 0; i < 8; i++) { mrow[i] = -1e30f; lrow[i] = 0.f; }

    for (int n0 = 0; n0 < SEQ; n0 += 64) {
        __syncthreads();   // prior tile's reads done (covers Qt staging on iter 0)
        // stage Kt transposed (bank = j, conflict-free)
#pragma unroll
        for (int it = 0; it < 8; it++) {
            int lin = it * 128 + tid;
            int j = lin & 63, dv = (lin >> 6) * 4;
            float4 v = *(const float4*)(Kp + (size_t)(n0 + j) * HD + dv);
            Kt[(dv + 0) * 64 + j] = v.x;
            Kt[(dv + 1) * 64 + j] = v.y;
            Kt[(dv + 2) * 64 + j] = v.z;
            Kt[(dv + 3) * 64 + j] = v.w;
        }
        // stage Vs row-major, stride 68
#pragma unroll
        for (int it = 0; it < 8; it++) {
            int lin = it * 128 + tid;
            int j = lin >> 4, dv = (lin & 15) * 4;
            *(float4*)(Vs + j * 68 + dv) = *(const float4*)(Vp + (size_t)(n0 + j) * HD + dv);
        }
        __syncthreads();

        // ---- QK: S[8q][8j] in registers, packed over j-pairs ----
        ull s2[8][4];
#pragma unroll
        for (int i = 0; i < 8; i++)
#pragma unroll
            for (int jp = 0; jp < 4; jp++) s2[i][jp] = 0ULL;

        const float* qb = Qt + q0;
        const float* kb = Kt + c0;
#pragma unroll 8
        for (int d = 0; d < 64; d++) {
            float4 qa = *(const float4*)(qb);
            float4 qc = *(const float4*)(qb + 4);
            ulonglong2 kA = *(const ulonglong2*)(kb);
            ulonglong2 kB = *(const ulonglong2*)(kb + 4);
            float a[8] = {qa.x, qa.y, qa.z, qa.w, qc.x, qc.y, qc.z, qc.w};
#pragma unroll
            for (int i = 0; i < 8; i++) {
                ull ad; PACK2(ad, a[i]);
                FMA2(s2[i][0], ad, kA.x);
                FMA2(s2[i][1], ad, kA.y);
                FMA2(s2[i][2], ad, kB.x);
                FMA2(s2[i][3], ad, kB.y);
            }
            qb += 128; kb += 64;
        }

        // ---- softmax (register + octet shuffles; no smem) ----
        float p[8][8];
#pragma unroll
        for (int i = 0; i < 8; i++)
#pragma unroll
            for (int jp = 0; jp < 4; jp++)
                UNPK2(p[i][2 * jp], p[i][2 * jp + 1], s2[i][jp]);

        float al[8], psum[8];
#pragma unroll
        for (int i = 0; i < 8; i++) {
            float mx = p[i][0];
#pragma unroll
            for (int jj = 1; jj < 8; jj++) mx = fmaxf(mx, p[i][jj]);
            mx = fmaxf(mx, __shfl_xor_sync(0xffffffffu, mx, 1, 8));
            mx = fmaxf(mx, __shfl_xor_sync(0xffffffffu, mx, 2, 8));
            mx = fmaxf(mx, __shfl_xor_sync(0xffffffffu, mx, 4, 8));
            float mnew = fmaxf(mrow[i], mx);
            al[i] = __expf(mrow[i] - mnew);
            mrow[i] = mnew;
            float s = 0.f;
#pragma unroll
            for (int jj = 0; jj < 8; jj++) {
                p[i][jj] = __expf(p[i][jj] - mnew);
                s += p[i][jj];
            }
            s += __shfl_xor_sync(0xffffffffu, s, 1, 8);
            s += __shfl_xor_sync(0xffffffffu, s, 2, 8);
            s += __shfl_xor_sync(0xffffffffu, s, 4, 8);
            psum[i] = s;
        }
#pragma unroll
        for (int i = 0; i < 8; i++) {
            lrow[i] = lrow[i] * al[i] + psum[i];
            ull a2; PACK2(a2, al[i]);
#pragma unroll
            for (int dp = 0; dp < 4; dp++) { ull t; MUL2(t, o2[i][dp], a2); o2[i][dp] = t; }
        }

        // ---- PV: O[8q][8d] += P · V, P broadcast within octet via shfl ----
        for (int js = 0; js < 8; js++) {
#pragma unroll
            for (int jj = 0; jj < 8; jj++) {
                int j = js * 8 + jj;
                const float* vr = Vs + j * 68 + c0;
                ulonglong2 vA = *(const ulonglong2*)(vr);
                ulonglong2 vB = *(const ulonglong2*)(vr + 4);
#pragma unroll
                for (int i = 0; i < 8; i++) {
                    float pj = __shfl_sync(0xffffffffu, p[i][jj], js, 8);
                    ull pd; PACK2(pd, pj);
                    FMA2(o2[i][0], pd, vA.x);
                    FMA2(o2[i][1], pd, vA.y);
                    FMA2(o2[i][2], pd, vB.x);
                    FMA2(o2[i][3], pd, vB.y);
                }
            }
        }
    }

    // ---- epilogue: normalize and store ----
#pragma unroll
    for (int i = 0; i < 8; i++) {
        float inv = 1.f / lrow[i];
        ull iv; PACK2(iv, inv);
        ull r0, r1, r2, r3;
        MUL2(r0, o2[i][0], iv); MUL2(r1, o2[i][1], iv);
        MUL2(r2, o2[i][2], iv); MUL2(r3, o2[i][3], iv);
        float* op = out + ((size_t)b * SEQ + m0 + q0 + i) * EMBED + h * HD + c0;
        ulonglong2 st0; st0.x = r0; st0.y = r1;
        ulonglong2 st1; st1.x = r2; st1.y = r3;
        *(ulonglong2*)(op)     = st0;
        *(ulonglong2*)(op + 4) = st1;
    }
}

// ---------------------------------------------------------------------------
extern "C" void kernel_launch(void* const* d_in, const int* in_sizes, int n_in,
                              void* d_out, int out_size)
{
    const float* x    = (const float*)d_in[0];   // (8,1024,768)
    const float* W    = (const float*)d_in[1];   // (2304,768)
    const float* bias = (const float*)d_in[2];   // (2304,)
    float* out = (float*)d_out;                  // (8,1024,768)

    dim3 ggrid(THREE_E / 128, M_TOTAL / 128);    // (18, 64)
    qkv_gemm_kernel<<<ggrid, 256>>>(x, W, bias);

    cudaFuncSetAttribute(attn_kernel, cudaFuncAttributeMaxDynamicSharedMemorySize,
                         (int)ATTN_SMEM);
    dim3 agrid(SEQ / 128, HEADS, BATCH);         // (8, 12, 8)
    attn_kernel<<<agrid, 128, ATTN_SMEM>>>(out);
}

// round 5
// speedup vs baseline: 3.6947x; 1.3122x over previous
#include <cuda_runtime.h>
#include <math.h>
#include <stdint.h>

#define EMBED   768
#define THREE_E 2304
#define HEADS   12
#define HD      64
#define BATCH   8
#define SEQ     1024
#define M_TOTAL (BATCH * SEQ)          // 8192
#define PER_BUF ((size_t)BATCH * HEADS * SEQ * HD)   // 6,291,456 floats

typedef unsigned long long ull;

// Scratch: Q,K stored [b][h][d][n] (d-major), V stored [b][h][n][d]
__device__ float g_qkv[3 * PER_BUF];

// ---- packed f32x2 helpers ----
#define PACK2(d, x)    asm("mov.b64 %0, {%1, %1};" : "=l"(d) : "f"(x))
#define UNPK2(lo,hi,v) asm("mov.b64 {%0, %1}, %2;" : "=f"(lo), "=f"(hi) : "l"(v))
#define FMA2(d, a, b)  asm("fma.rn.f32x2 %0, %1, %2, %0;" : "+l"(d) : "l"(a), "l"(b))
#define MUL2(d, a, b)  asm("mul.rn.f32x2 %0, %1, %2;" : "=l"(d) : "l"(a), "l"(b))

// ---- cp.async helpers ----
__device__ __forceinline__ uint32_t smem_u32(const void* p) {
    return (uint32_t)__cvta_generic_to_shared(p);
}
__device__ __forceinline__ void cpa16(uint32_t s, const void* g) {
    asm volatile("cp.async.cg.shared.global [%0], [%1], 16;" :: "r"(s), "l"(g));
}
#define CPA_COMMIT() asm volatile("cp.async.commit_group;")
#define CPA_WAIT(n)  asm volatile("cp.async.wait_group %0;" :: "n"(n))

// ---------------------------------------------------------------------------
// Kernel 1: QKV projection, double-buffered smem, f32x2 FMA.
// 128x128 tile, BK=8, 256 threads, 8x8 microtile. One sync per K-step.
// Epilogue: Q,K scattered d-major; V row-major.
// ---------------------------------------------------------------------------
__global__ __launch_bounds__(256, 2) void qkv_gemm_kernel(
    const float* __restrict__ X, const float* __restrict__ W,
    const float* __restrict__ bias)
{
    __shared__ float Xs[2][8][128];
    __shared__ float Ws[2][8][128];

    const int tid = threadIdx.x;
    const int m0 = blockIdx.y * 128;
    const int n0 = blockIdx.x * 128;
    const int tx = tid & 15;
    const int ty = tid >> 4;
    const int lrow = tid >> 1;
    const int lvec = (tid & 1) * 4;

    ull acc2[4][8];
#pragma unroll
    for (int i = 0; i < 4; i++)
#pragma unroll
        for (int j = 0; j < 8; j++) acc2[i][j] = 0ULL;

    const float* xptr = X + (size_t)(m0 + lrow) * EMBED + lvec;
    const float* wptr = W + (size_t)(n0 + lrow) * EMBED + lvec;

    // prologue: stage k0=0 into buf 0
    {
        float4 xv = *(const float4*)(xptr);
        float4 wv = *(const float4*)(wptr);
        Xs[0][lvec + 0][lrow] = xv.x; Xs[0][lvec + 1][lrow] = xv.y;
        Xs[0][lvec + 2][lrow] = xv.z; Xs[0][lvec + 3][lrow] = xv.w;
        Ws[0][lvec + 0][lrow] = wv.x; Ws[0][lvec + 1][lrow] = wv.y;
        Ws[0][lvec + 2][lrow] = wv.z; Ws[0][lvec + 3][lrow] = wv.w;
    }
    __syncthreads();

    for (int k0 = 0; k0 < EMBED; k0 += 8) {
        const int cur = (k0 >> 3) & 1;
        float4 nxv, nwv;
        const bool more = (k0 + 8) < EMBED;
        if (more) {
            nxv = *(const float4*)(xptr + k0 + 8);
            nwv = *(const float4*)(wptr + k0 + 8);
        }
#pragma unroll
        for (int k = 0; k < 8; k++) {
            ulonglong2 xa = *(const ulonglong2*)(&Xs[cur][k][ty * 8]);
            ulonglong2 xb = *(const ulonglong2*)(&Xs[cur][k][ty * 8 + 4]);
            float4 w0 = *(const float4*)(&Ws[cur][k][tx * 8]);
            float4 w1 = *(const float4*)(&Ws[cur][k][tx * 8 + 4]);
            ull wd[8];
            PACK2(wd[0], w0.x); PACK2(wd[1], w0.y);
            PACK2(wd[2], w0.z); PACK2(wd[3], w0.w);
            PACK2(wd[4], w1.x); PACK2(wd[5], w1.y);
            PACK2(wd[6], w1.z); PACK2(wd[7], w1.w);
            ull xp[4] = {xa.x, xa.y, xb.x, xb.y};
#pragma unroll
            for (int ip = 0; ip < 4; ip++)
#pragma unroll
                for (int j = 0; j < 8; j++)
                    FMA2(acc2[ip][j], xp[ip], wd[j]);
        }
        if (more) {
            const int nxt = cur ^ 1;
            Xs[nxt][lvec + 0][lrow] = nxv.x; Xs[nxt][lvec + 1][lrow] = nxv.y;
            Xs[nxt][lvec + 2][lrow] = nxv.z; Xs[nxt][lvec + 3][lrow] = nxv.w;
            Ws[nxt][lvec + 0][lrow] = nwv.x; Ws[nxt][lvec + 1][lrow] = nwv.y;
            Ws[nxt][lvec + 2][lrow] = nwv.z; Ws[nxt][lvec + 3][lrow] = nwv.w;
        }
        __syncthreads();
    }

    float bb[8];
#pragma unroll
    for (int j = 0; j < 8; j++) bb[j] = bias[n0 + tx * 8 + j];

#pragma unroll
    for (int ip = 0; ip < 4; ip++) {
#pragma unroll
        for (int j = 0; j < 8; j++) {
            float v0, v1;
            UNPK2(v0, v1, acc2[ip][j]);
            int c = n0 + tx * 8 + j;
            int hh = c / 192;
            int r  = c - hh * 192;
            int which = r >> 6;
            int d = r & 63;
#pragma unroll
            for (int dd = 0; dd < 2; dd++) {
                int m = m0 + ty * 8 + ip * 2 + dd;
                int bidx = m >> 10;
                int n    = m & (SEQ - 1);
                float val = (dd ? v1 : v0) + bb[j];
                size_t idx;
                if (which == 2) {  // V: [b][h][n][d]
                    idx = 2 * PER_BUF + (((size_t)bidx * HEADS + hh) * SEQ + n) * HD + d;
                } else {           // Q,K: [b][h][d][n]
                    idx = (size_t)which * PER_BUF +
                          (((size_t)bidx * HEADS + hh) * HD + d) * SEQ + n;
                }
                g_qkv[idx] = val;
            }
        }
    }
}

// ---------------------------------------------------------------------------
// Kernel 2: flash attention, fp32 f32x2, cp.async double-buffered K/V.
// CTA = (b, h, 128 queries). 128 threads = 16(q-blocks) x 8(col-blocks).
// smem: Qt[64][128] (d-major), 2x Kt[64][64] (d-major), 2x Vs[64][68].
// ---------------------------------------------------------------------------
#define SM_QT   0
#define SM_KT0  8192
#define SM_KT1  12288
#define SM_VS0  16384
#define SM_VS1  20736
#define SM_TOTF 25088
#define ATTN_SMEM (SM_TOTF * sizeof(float))   // 100,352 B

__global__ __launch_bounds__(128) void attn_kernel(float* __restrict__ out)
{
    extern __shared__ float sm[];
    const uint32_t sbase = smem_u32(sm);

    const int b  = blockIdx.z;
    const int h  = blockIdx.y;
    const int m0 = blockIdx.x * 128;
    const size_t bh = (size_t)b * HEADS + h;
    const float* Qg = g_qkv + bh * HD * SEQ;                 // [d][n]
    const float* Kg = g_qkv + PER_BUF + bh * HD * SEQ;       // [d][n]
    const float* Vg = g_qkv + 2 * PER_BUF + bh * SEQ * HD;   // [n][d]

    const int tid = threadIdx.x;
    const int tx  = tid & 7;
    const int ty  = tid >> 3;
    const int q0  = ty * 8;
    const int c0  = tx * 8;

    // ---- prologue: cp.async Q tile + KV tile 0 ----
    // Qt: 64 rows x 128 floats
#pragma unroll
    for (int it = 0; it < 16; it++) {
        int c = it * 128 + tid;
        int row = c >> 5, off = (c & 31) * 4;
        cpa16(sbase + (uint32_t)(row * 128 + off) * 4,
              Qg + (size_t)row * SEQ + m0 + off);
    }
    // KV tile 0 -> buf 0
#pragma unroll
    for (int it = 0; it < 8; it++) {
        int c = it * 128 + tid;
        int row = c >> 4, off = (c & 15) * 4;
        cpa16(sbase + (uint32_t)(SM_KT0 + row * 64 + off) * 4,
              Kg + (size_t)row * SEQ + 0 + off);
        cpa16(sbase + (uint32_t)(SM_VS0 + row * 68 + off) * 4,
              Vg + (size_t)(0 + row) * HD + off);
    }
    CPA_COMMIT();

    ull o2[8][4];
#pragma unroll
    for (int i = 0; i < 8; i++)
#pragma unroll
        for (int dp = 0; dp < 4; dp++) o2[i][dp] = 0ULL;
    float mrow[8], lrow[8];
#pragma unroll
    for (int i = 0; i < 8; i++) { mrow[i] = -1e30f; lrow[i] = 0.f; }

    ull scl2; PACK2(scl2, 0.125f);   // 1/sqrt(64)

    const float* Qt = sm;
    for (int t = 0; t < SEQ / 64; t++) {
        const int buf = t & 1;
        // issue next tile into the other buffer
        if (t + 1 < SEQ / 64) {
            const int n1 = (t + 1) * 64;
            const uint32_t kdst = (buf ? SM_KT0 : SM_KT1);
            const uint32_t vdst = (buf ? SM_VS0 : SM_VS1);
#pragma unroll
            for (int it = 0; it < 8; it++) {
                int c = it * 128 + tid;
                int row = c >> 4, off = (c & 15) * 4;
                cpa16(sbase + (kdst + (uint32_t)(row * 64 + off)) * 4,
                      Kg + (size_t)row * SEQ + n1 + off);
                cpa16(sbase + (vdst + (uint32_t)(row * 68 + off)) * 4,
                      Vg + (size_t)(n1 + row) * HD + off);
            }
            CPA_COMMIT();
            CPA_WAIT(1);
        } else {
            CPA_WAIT(0);
        }
        __syncthreads();   // current tile visible to all threads

        const float* Kt = sm + (buf ? SM_KT1 : SM_KT0);
        const float* Vs = sm + (buf ? SM_VS1 : SM_VS0);

        // ---- QK: S[8q][8j] in registers ----
        ull s2[8][4];
#pragma unroll
        for (int i = 0; i < 8; i++)
#pragma unroll
            for (int jp = 0; jp < 4; jp++) s2[i][jp] = 0ULL;

        const float* qb = Qt + q0;
        const float* kb = Kt + c0;
#pragma unroll 8
        for (int d = 0; d < 64; d++) {
            float4 qa = *(const float4*)(qb);
            float4 qc = *(const float4*)(qb + 4);
            ulonglong2 kA = *(const ulonglong2*)(kb);
            ulonglong2 kB = *(const ulonglong2*)(kb + 4);
            float a[8] = {qa.x, qa.y, qa.z, qa.w, qc.x, qc.y, qc.z, qc.w};
#pragma unroll
            for (int i = 0; i < 8; i++) {
                ull ad; PACK2(ad, a[i]);
                FMA2(s2[i][0], ad, kA.x);
                FMA2(s2[i][1], ad, kA.y);
                FMA2(s2[i][2], ad, kB.x);
                FMA2(s2[i][3], ad, kB.y);
            }
            qb += 128; kb += 64;
        }
        // scale by 1/sqrt(d)
#pragma unroll
        for (int i = 0; i < 8; i++)
#pragma unroll
            for (int jp = 0; jp < 4; jp++) {
                ull tt; MUL2(tt, s2[i][jp], scl2); s2[i][jp] = tt;
            }

        // ---- softmax (registers + octet shuffles) ----
        float p[8][8];
#pragma unroll
        for (int i = 0; i < 8; i++)
#pragma unroll
            for (int jp = 0; jp < 4; jp++)
                UNPK2(p[i][2 * jp], p[i][2 * jp + 1], s2[i][jp]);

        float al[8], psum[8];
#pragma unroll
        for (int i = 0; i < 8; i++) {
            float mx = p[i][0];
#pragma unroll
            for (int jj = 1; jj < 8; jj++) mx = fmaxf(mx, p[i][jj]);
            mx = fmaxf(mx, __shfl_xor_sync(0xffffffffu, mx, 1, 8));
            mx = fmaxf(mx, __shfl_xor_sync(0xffffffffu, mx, 2, 8));
            mx = fmaxf(mx, __shfl_xor_sync(0xffffffffu, mx, 4, 8));
            float mnew = fmaxf(mrow[i], mx);
            al[i] = __expf(mrow[i] - mnew);
            mrow[i] = mnew;
            float s = 0.f;
#pragma unroll
            for (int jj = 0; jj < 8; jj++) {
                p[i][jj] = __expf(p[i][jj] - mnew);
                s += p[i][jj];
            }
            s += __shfl_xor_sync(0xffffffffu, s, 1, 8);
            s += __shfl_xor_sync(0xffffffffu, s, 2, 8);
            s += __shfl_xor_sync(0xffffffffu, s, 4, 8);
            psum[i] = s;
        }
#pragma unroll
        for (int i = 0; i < 8; i++) {
            lrow[i] = lrow[i] * al[i] + psum[i];
            ull a2; PACK2(a2, al[i]);
#pragma unroll
            for (int dp = 0; dp < 4; dp++) { ull tt; MUL2(tt, o2[i][dp], a2); o2[i][dp] = tt; }
        }

        // ---- PV: O[8q][8d] += P . V (P broadcast within octet via shfl) ----
        for (int js = 0; js < 8; js++) {
#pragma unroll
            for (int jj = 0; jj < 8; jj++) {
                int j = js * 8 + jj;
                const float* vr = Vs + j * 68 + c0;
                ulonglong2 vA = *(const ulonglong2*)(vr);
                ulonglong2 vB = *(const ulonglong2*)(vr + 4);
#pragma unroll
                for (int i = 0; i < 8; i++) {
                    float pj = __shfl_sync(0xffffffffu, p[i][jj], js, 8);
                    ull pd; PACK2(pd, pj);
                    FMA2(o2[i][0], pd, vA.x);
                    FMA2(o2[i][1], pd, vA.y);
                    FMA2(o2[i][2], pd, vB.x);
                    FMA2(o2[i][3], pd, vB.y);
                }
            }
        }
        __syncthreads();   // all reads of this buffer done before refill
    }

    // ---- epilogue: normalize and store ----
#pragma unroll
    for (int i = 0; i < 8; i++) {
        float inv = 1.f / lrow[i];
        ull iv; PACK2(iv, inv);
        ull r0, r1, r2, r3;
        MUL2(r0, o2[i][0], iv); MUL2(r1, o2[i][1], iv);
        MUL2(r2, o2[i][2], iv); MUL2(r3, o2[i][3], iv);
        float* op = out + ((size_t)b * SEQ + m0 + q0 + i) * EMBED + h * HD + c0;
        ulonglong2 st0; st0.x = r0; st0.y = r1;
        ulonglong2 st1; st1.x = r2; st1.y = r3;
        *(ulonglong2*)(op)     = st0;
        *(ulonglong2*)(op + 4) = st1;
    }
}

// ---------------------------------------------------------------------------
extern "C" void kernel_launch(void* const* d_in, const int* in_sizes, int n_in,
                              void* d_out, int out_size)
{
    const float* x    = (const float*)d_in[0];   // (8,1024,768)
    const float* W    = (const float*)d_in[1];   // (2304,768)
    const float* bias = (const float*)d_in[2];   // (2304,)
    float* out = (float*)d_out;                  // (8,1024,768)

    dim3 ggrid(THREE_E / 128, M_TOTAL / 128);    // (18, 64)
    qkv_gemm_kernel<<<ggrid, 256>>>(x, W, bias);

    cudaFuncSetAttribute(attn_kernel, cudaFuncAttributeMaxDynamicSharedMemorySize,
                         (int)ATTN_SMEM);
    dim3 agrid(SEQ / 128, HEADS, BATCH);         // (8, 12, 8)
    attn_kernel<<<agrid, 128, ATTN_SMEM>>>(out);
}

// round 7
// speedup vs baseline: 5.8064x; 1.5715x over previous
#include <cuda_runtime.h>
#include <math.h>
#include <stdint.h>

#define EMBED   768
#define THREE_E 2304
#define HEADS   12
#define HD      64
#define BATCH   8
#define SEQ     1024
#define M_TOTAL (BATCH * SEQ)          // 8192
#define PER_BUF ((size_t)BATCH * HEADS * SEQ * HD)

typedef unsigned long long ull;

// Scratch: Q,K stored [b][h][d][n] (d-major), V stored [b][h][n][d]
__device__ float g_qkv[3 * PER_BUF];

// ---- packed f32x2 helpers ----
#define PACK2(d, x)    asm("mov.b64 %0, {%1, %1};" : "=l"(d) : "f"(x))
#define UNPK2(lo,hi,v) asm("mov.b64 {%0, %1}, %2;" : "=f"(lo), "=f"(hi) : "l"(v))
#define FMA2(d, a, b)  asm("fma.rn.f32x2 %0, %1, %2, %0;" : "+l"(d) : "l"(a), "l"(b))
#define MUL2(d, a, b)  asm("mul.rn.f32x2 %0, %1, %2;" : "=l"(d) : "l"(a), "l"(b))

// ---- cp.async ----
__device__ __forceinline__ uint32_t smem_u32(const void* p) {
    return (uint32_t)__cvta_generic_to_shared(p);
}
__device__ __forceinline__ void cpa16(uint32_t s, const void* g) {
    asm volatile("cp.async.cg.shared.global [%0], [%1], 16;" :: "r"(s), "l"(g));
}
#define CPA_COMMIT() asm volatile("cp.async.commit_group;")
#define CPA_WAIT(n)  asm volatile("cp.async.wait_group %0;" :: "n"(n))

// ---- tf32 ----
__device__ __forceinline__ uint32_t f2tf32(float f) {
    uint32_t r; asm("cvt.rna.tf32.f32 %0, %1;" : "=r"(r) : "f"(f)); return r;
}
#define MMA_TF32(c, a, b) \
    asm volatile("mma.sync.aligned.m16n8k8.row.col.f32.tf32.tf32.f32 " \
        "{%0,%1,%2,%3},{%4,%5,%6,%7},{%8,%9},{%0,%1,%2,%3};" \
        : "+f"((c)[0]), "+f"((c)[1]), "+f"((c)[2]), "+f"((c)[3]) \
        : "r"((a)[0]), "r"((a)[1]), "r"((a)[2]), "r"((a)[3]), \
          "r"((b)[0]), "r"((b)[1]))

// ---------------------------------------------------------------------------
// Kernel 1: QKV projection, tf32 tensor-core GEMM.
// CTA 128x128, BK=32, 256 threads = 8 warps (2x4), warp tile 64x32.
// A = X row-major, B = W row-major (n,k) read as col-major k x n fragments.
// ---------------------------------------------------------------------------
#define GPAD 36
#define G_ABUF (128 * GPAD)            // 4608 floats per buffer
#define G_BS   (2 * G_ABUF)
#define GEMM_SMEM (4 * G_ABUF * sizeof(float))   // 73728 B

__device__ __forceinline__ void qkv_scatter(float val, int m, int c) {
    int bidx = m >> 10;
    int n    = m & (SEQ - 1);
    int hh = c / 192;
    int r  = c - hh * 192;
    int which = r >> 6;
    int d = r & 63;
    size_t idx;
    if (which == 2)   // V: [b][h][n][d]
        idx = 2 * PER_BUF + (((size_t)bidx * HEADS + hh) * SEQ + n) * HD + d;
    else              // Q,K: [b][h][d][n]
        idx = (size_t)which * PER_BUF +
              (((size_t)bidx * HEADS + hh) * HD + d) * SEQ + n;
    g_qkv[idx] = val;
}

__global__ __launch_bounds__(256, 2) void qkv_gemm_kernel(
    const float* __restrict__ X, const float* __restrict__ W,
    const float* __restrict__ bias)
{
    extern __shared__ float gsm[];
    const uint32_t sb = smem_u32(gsm);

    const int tid  = threadIdx.x;
    const int lane = tid & 31;
    const int wid  = tid >> 5;
    const int wm   = wid >> 2;        // 0..1
    const int wn   = wid & 3;         // 0..3
    const int g    = lane >> 2;       // groupID 0..7
    const int tg   = lane & 3;        // thread-in-group 0..3
    const int m0 = blockIdx.y * 128;
    const int n0 = blockIdx.x * 128;

    float acc[4][4][4];
#pragma unroll
    for (int mt = 0; mt < 4; mt++)
#pragma unroll
        for (int nt = 0; nt < 4; nt++)
#pragma unroll
            for (int k = 0; k < 4; k++) acc[mt][nt][k] = 0.f;

    // prologue: stage k0=0 into buf 0
    {
#pragma unroll
        for (int it = 0; it < 4; it++) {
            int chunk = it * 256 + tid;        // 0..1023
            int row = chunk >> 3, f4 = (chunk & 7) * 4;
            cpa16(sb + (uint32_t)(row * GPAD + f4) * 4,
                  X + (size_t)(m0 + row) * EMBED + f4);
        }
#pragma unroll
        for (int it = 0; it < 4; it++) {
            int chunk = it * 256 + tid;
            int row = chunk >> 3, f4 = (chunk & 7) * 4;
            cpa16(sb + (uint32_t)(G_BS + row * GPAD + f4) * 4,
                  W + (size_t)(n0 + row) * EMBED + f4);
        }
        CPA_COMMIT();
    }

    for (int t = 0; t < EMBED / 32; t++) {
        if (t + 1 < EMBED / 32) {
            const int nb = (t + 1) & 1;
            const int k0 = (t + 1) * 32;
#pragma unroll
            for (int it = 0; it < 4; it++) {
                int chunk = it * 256 + tid;
                int row = chunk >> 3, f4 = (chunk & 7) * 4;
                cpa16(sb + (uint32_t)(nb * G_ABUF + row * GPAD + f4) * 4,
                      X + (size_t)(m0 + row) * EMBED + k0 + f4);
            }
#pragma unroll
            for (int it = 0; it < 4; it++) {
                int chunk = it * 256 + tid;
                int row = chunk >> 3, f4 = (chunk & 7) * 4;
                cpa16(sb + (uint32_t)(G_BS + nb * G_ABUF + row * GPAD + f4) * 4,
                      W + (size_t)(n0 + row) * EMBED + k0 + f4);
            }
            CPA_COMMIT();
            CPA_WAIT(1);
        } else {
            CPA_WAIT(0);
        }
        __syncthreads();

        const float* Ab = gsm + (t & 1) * G_ABUF;
        const float* Bb = gsm + G_BS + (t & 1) * G_ABUF;

#pragma unroll
        for (int ks = 0; ks < 4; ks++) {
            uint32_t af[4][4], bf[4][2];
#pragma unroll
            for (int mt = 0; mt < 4; mt++) {
                const float* ap = Ab + (wm * 64 + mt * 16 + g) * GPAD + ks * 8 + tg;
                af[mt][0] = f2tf32(ap[0]);
                af[mt][1] = f2tf32(ap[8 * GPAD]);
                af[mt][2] = f2tf32(ap[4]);
                af[mt][3] = f2tf32(ap[8 * GPAD + 4]);
            }
#pragma unroll
            for (int nt = 0; nt < 4; nt++) {
                const float* bp = Bb + (wn * 32 + nt * 8 + g) * GPAD + ks * 8 + tg;
                bf[nt][0] = f2tf32(bp[0]);
                bf[nt][1] = f2tf32(bp[4]);
            }
#pragma unroll
            for (int mt = 0; mt < 4; mt++)
#pragma unroll
                for (int nt = 0; nt < 4; nt++)
                    MMA_TF32(acc[mt][nt], af[mt], bf[nt]);
        }
        __syncthreads();
    }

    // epilogue: add bias, scatter to g_qkv
#pragma unroll
    for (int mt = 0; mt < 4; mt++) {
#pragma unroll
        for (int nt = 0; nt < 4; nt++) {
            int row = m0 + wm * 64 + mt * 16 + g;
            int col = n0 + wn * 32 + nt * 8 + 2 * tg;
            float b0 = bias[col], b1 = bias[col + 1];
            qkv_scatter(acc[mt][nt][0] + b0, row,     col);
            qkv_scatter(acc[mt][nt][1] + b1, row,     col + 1);
            qkv_scatter(acc[mt][nt][2] + b0, row + 8, col);
            qkv_scatter(acc[mt][nt][3] + b1, row + 8, col + 1);
        }
    }
}

// ---------------------------------------------------------------------------
// Kernel 2: flash attention (Round-5 known-good version).
// fp32 f32x2, cp.async double-buffered K/V, shfl-based P exchange.
// CTA = (b, h, 128 queries). 128 threads = 16(q-blocks) x 8(col-blocks).
// smem: Qt[64][128] (d-major), 2x Kt[64][64] (d-major), 2x Vs[64][68].
// ---------------------------------------------------------------------------
#define SM_QT   0
#define SM_KT0  8192
#define SM_KT1  12288
#define SM_VS0  16384
#define SM_VS1  20736
#define SM_TOTF 25088
#define ATTN_SMEM (SM_TOTF * sizeof(float))   // 100,352 B

__global__ __launch_bounds__(128) void attn_kernel(float* __restrict__ out)
{
    extern __shared__ float sm[];
    const uint32_t sbase = smem_u32(sm);

    const int b  = blockIdx.z;
    const int h  = blockIdx.y;
    const int m0 = blockIdx.x * 128;
    const size_t bh = (size_t)b * HEADS + h;
    const float* Qg = g_qkv + bh * HD * SEQ;                 // [d][n]
    const float* Kg = g_qkv + PER_BUF + bh * HD * SEQ;       // [d][n]
    const float* Vg = g_qkv + 2 * PER_BUF + bh * SEQ * HD;   // [n][d]

    const int tid = threadIdx.x;
    const int tx  = tid & 7;
    const int ty  = tid >> 3;
    const int q0  = ty * 8;
    const int c0  = tx * 8;

    // ---- prologue: cp.async Q tile + KV tile 0 ----
#pragma unroll
    for (int it = 0; it < 16; it++) {
        int c = it * 128 + tid;
        int row = c >> 5, off = (c & 31) * 4;
        cpa16(sbase + (uint32_t)(row * 128 + off) * 4,
              Qg + (size_t)row * SEQ + m0 + off);
    }
#pragma unroll
    for (int it = 0; it < 8; it++) {
        int c = it * 128 + tid;
        int row = c >> 4, off = (c & 15) * 4;
        cpa16(sbase + (uint32_t)(SM_KT0 + row * 64 + off) * 4,
              Kg + (size_t)row * SEQ + 0 + off);
        cpa16(sbase + (uint32_t)(SM_VS0 + row * 68 + off) * 4,
              Vg + (size_t)(0 + row) * HD + off);
    }
    CPA_COMMIT();

    ull o2[8][4];
#pragma unroll
    for (int i = 0; i < 8; i++)
#pragma unroll
        for (int dp = 0; dp < 4; dp++) o2[i][dp] = 0ULL;
    float mrow[8], lrow[8];
#pragma unroll
    for (int i = 0; i < 8; i++) { mrow[i] = -1e30f; lrow[i] = 0.f; }

    ull scl2; PACK2(scl2, 0.125f);   // 1/sqrt(64)

    const float* Qt = sm;
    for (int t = 0; t < SEQ / 64; t++) {
        const int buf = t & 1;
        if (t + 1 < SEQ / 64) {
            const int n1 = (t + 1) * 64;
            const uint32_t kdst = (buf ? SM_KT0 : SM_KT1);
            const uint32_t vdst = (buf ? SM_VS0 : SM_VS1);
#pragma unroll
            for (int it = 0; it < 8; it++) {
                int c = it * 128 + tid;
                int row = c >> 4, off = (c & 15) * 4;
                cpa16(sbase + (kdst + (uint32_t)(row * 64 + off)) * 4,
                      Kg + (size_t)row * SEQ + n1 + off);
                cpa16(sbase + (vdst + (uint32_t)(row * 68 + off)) * 4,
                      Vg + (size_t)(n1 + row) * HD + off);
            }
            CPA_COMMIT();
            CPA_WAIT(1);
        } else {
            CPA_WAIT(0);
        }
        __syncthreads();

        const float* Kt = sm + (buf ? SM_KT1 : SM_KT0);
        const float* Vs = sm + (buf ? SM_VS1 : SM_VS0);

        // ---- QK: S[8q][8j] in registers ----
        ull s2[8][4];
#pragma unroll
        for (int i = 0; i < 8; i++)
#pragma unroll
            for (int jp = 0; jp < 4; jp++) s2[i][jp] = 0ULL;

        const float* qb = Qt + q0;
        const float* kb = Kt + c0;
#pragma unroll 8
        for (int d = 0; d < 64; d++) {
            float4 qa = *(const float4*)(qb);
            float4 qc = *(const float4*)(qb + 4);
            ulonglong2 kA = *(const ulonglong2*)(kb);
            ulonglong2 kB = *(const ulonglong2*)(kb + 4);
            float a[8] = {qa.x, qa.y, qa.z, qa.w, qc.x, qc.y, qc.z, qc.w};
#pragma unroll
            for (int i = 0; i < 8; i++) {
                ull ad; PACK2(ad, a[i]);
                FMA2(s2[i][0], ad, kA.x);
                FMA2(s2[i][1], ad, kA.y);
                FMA2(s2[i][2], ad, kB.x);
                FMA2(s2[i][3], ad, kB.y);
            }
            qb += 128; kb += 64;
        }
#pragma unroll
        for (int i = 0; i < 8; i++)
#pragma unroll
            for (int jp = 0; jp < 4; jp++) {
                ull tt; MUL2(tt, s2[i][jp], scl2); s2[i][jp] = tt;
            }

        // ---- softmax (registers + octet shuffles) ----
        float p[8][8];
#pragma unroll
        for (int i = 0; i < 8; i++)
#pragma unroll
            for (int jp = 0; jp < 4; jp++)
                UNPK2(p[i][2 * jp], p[i][2 * jp + 1], s2[i][jp]);

        float al[8], psum[8];
#pragma unroll
        for (int i = 0; i < 8; i++) {
            float mx = p[i][0];
#pragma unroll
            for (int jj = 1; jj < 8; jj++) mx = fmaxf(mx, p[i][jj]);
            mx = fmaxf(mx, __shfl_xor_sync(0xffffffffu, mx, 1, 8));
            mx = fmaxf(mx, __shfl_xor_sync(0xffffffffu, mx, 2, 8));
            mx = fmaxf(mx, __shfl_xor_sync(0xffffffffu, mx, 4, 8));
            float mnew = fmaxf(mrow[i], mx);
            al[i] = __expf(mrow[i] - mnew);
            mrow[i] = mnew;
            float s = 0.f;
#pragma unroll
            for (int jj = 0; jj < 8; jj++) {
                p[i][jj] = __expf(p[i][jj] - mnew);
                s += p[i][jj];
            }
            s += __shfl_xor_sync(0xffffffffu, s, 1, 8);
            s += __shfl_xor_sync(0xffffffffu, s, 2, 8);
            s += __shfl_xor_sync(0xffffffffu, s, 4, 8);
            psum[i] = s;
        }
#pragma unroll
        for (int i = 0; i < 8; i++) {
            lrow[i] = lrow[i] * al[i] + psum[i];
            ull a2; PACK2(a2, al[i]);
#pragma unroll
            for (int dp = 0; dp < 4; dp++) { ull tt; MUL2(tt, o2[i][dp], a2); o2[i][dp] = tt; }
        }

        // ---- PV: O[8q][8d] += P . V (P broadcast within octet via shfl) ----
        for (int js = 0; js < 8; js++) {
#pragma unroll
            for (int jj = 0; jj < 8; jj++) {
                int j = js * 8 + jj;
                const float* vr = Vs + j * 68 + c0;
                ulonglong2 vA = *(const ulonglong2*)(vr);
                ulonglong2 vB = *(const ulonglong2*)(vr + 4);
#pragma unroll
                for (int i = 0; i < 8; i++) {
                    float pj = __shfl_sync(0xffffffffu, p[i][jj], js, 8);
                    ull pd; PACK2(pd, pj);
                    FMA2(o2[i][0], pd, vA.x);
                    FMA2(o2[i][1], pd, vA.y);
                    FMA2(o2[i][2], pd, vB.x);
                    FMA2(o2[i][3], pd, vB.y);
                }
            }
        }
        __syncthreads();   // all reads of this buffer done before refill
    }

    // ---- epilogue: normalize and store ----
#pragma unroll
    for (int i = 0; i < 8; i++) {
        float inv = 1.f / lrow[i];
        ull iv; PACK2(iv, inv);
        ull r0, r1, r2, r3;
        MUL2(r0, o2[i][0], iv); MUL2(r1, o2[i][1], iv);
        MUL2(r2, o2[i][2], iv); MUL2(r3, o2[i][3], iv);
        float* op = out + ((size_t)b * SEQ + m0 + q0 + i) * EMBED + h * HD + c0;
        ulonglong2 st0; st0.x = r0; st0.y = r1;
        ulonglong2 st1; st1.x = r2; st1.y = r3;
        *(ulonglong2*)(op)     = st0;
        *(ulonglong2*)(op + 4) = st1;
    }
}

// ---------------------------------------------------------------------------
extern "C" void kernel_launch(void* const* d_in, const int* in_sizes, int n_in,
                              void* d_out, int out_size)
{
    const float* x    = (const float*)d_in[0];
    const float* W    = (const float*)d_in[1];
    const float* bias = (const float*)d_in[2];
    float* out = (float*)d_out;

    cudaFuncSetAttribute(qkv_gemm_kernel, cudaFuncAttributeMaxDynamicSharedMemorySize,
                         (int)GEMM_SMEM);
    dim3 ggrid(THREE_E / 128, M_TOTAL / 128);    // (18, 64)
    qkv_gemm_kernel<<<ggrid, 256, GEMM_SMEM>>>(x, W, bias);

    cudaFuncSetAttribute(attn_kernel, cudaFuncAttributeMaxDynamicSharedMemorySize,
                         (int)ATTN_SMEM);
    dim3 agrid(SEQ / 128, HEADS, BATCH);         // (8, 12, 8)
    attn_kernel<<<agrid, 128, ATTN_SMEM>>>(out);
}

// round 8
// speedup vs baseline: 12.4305x; 2.1408x over previous
#include <cuda_runtime.h>
#include <math.h>
#include <stdint.h>

#define EMBED   768
#define THREE_E 2304
#define HEADS   12
#define HD      64
#define BATCH   8
#define SEQ     1024
#define M_TOTAL (BATCH * SEQ)          // 8192
#define PER_BUF ((size_t)BATCH * HEADS * SEQ * HD)

// Scratch: Q [b][h][n][d] (pre-scaled 1/8, tf32-rounded)
//          K [b][h][d][n] (tf32-rounded)
//          V [b][h][n][d] (tf32-rounded)
__device__ float g_qkv[3 * PER_BUF];

// ---- cp.async ----
__device__ __forceinline__ uint32_t smem_u32(const void* p) {
    return (uint32_t)__cvta_generic_to_shared(p);
}
__device__ __forceinline__ void cpa16(uint32_t s, const void* g) {
    asm volatile("cp.async.cg.shared.global [%0], [%1], 16;" :: "r"(s), "l"(g));
}
#define CPA_COMMIT() asm volatile("cp.async.commit_group;")
#define CPA_WAIT(n)  asm volatile("cp.async.wait_group %0;" :: "n"(n))

// ---- tf32 ----
__device__ __forceinline__ uint32_t f2tf32(float f) {
    uint32_t r; asm("cvt.rna.tf32.f32 %0, %1;" : "=r"(r) : "f"(f)); return r;
}
#define MMA_TF32(c, a, b) \
    asm volatile("mma.sync.aligned.m16n8k8.row.col.f32.tf32.tf32.f32 " \
        "{%0,%1,%2,%3},{%4,%5,%6,%7},{%8,%9},{%0,%1,%2,%3};" \
        : "+f"((c)[0]), "+f"((c)[1]), "+f"((c)[2]), "+f"((c)[3]) \
        : "r"((a)[0]), "r"((a)[1]), "r"((a)[2]), "r"((a)[3]), \
          "r"((b)[0]), "r"((b)[1]))

// ---------------------------------------------------------------------------
// Kernel 1: QKV projection, tf32 tensor-core GEMM (unchanged mainloop).
// Epilogue: tf32-round everything; pre-scale Q by 1/sqrt(64).
// ---------------------------------------------------------------------------
#define GPAD 36
#define G_ABUF (128 * GPAD)
#define G_BS   (2 * G_ABUF)
#define GEMM_SMEM (4 * G_ABUF * sizeof(float))   // 73728 B

__device__ __forceinline__ void qkv_scatter(float val, int m, int c) {
    int bidx = m >> 10;
    int n    = m & (SEQ - 1);
    int hh = c / 192;
    int r  = c - hh * 192;
    int which = r >> 6;
    int d = r & 63;
    if (which == 0) val *= 0.125f;                 // fold 1/sqrt(64) into Q
    val = __uint_as_float(f2tf32(val));            // pre-round to tf32
    size_t idx;
    if (which == 1)   // K: [b][h][d][n]
        idx = PER_BUF + (((size_t)bidx * HEADS + hh) * HD + d) * SEQ + n;
    else              // Q (0), V (2): [b][h][n][d]
        idx = (size_t)which * PER_BUF +
              (((size_t)bidx * HEADS + hh) * SEQ + n) * HD + d;
    g_qkv[idx] = val;
}

__global__ __launch_bounds__(256, 2) void qkv_gemm_kernel(
    const float* __restrict__ X, const float* __restrict__ W,
    const float* __restrict__ bias)
{
    extern __shared__ float gsm[];
    const uint32_t sb = smem_u32(gsm);

    const int tid  = threadIdx.x;
    const int lane = tid & 31;
    const int wid  = tid >> 5;
    const int wm   = wid >> 2;
    const int wn   = wid & 3;
    const int g    = lane >> 2;
    const int tg   = lane & 3;
    const int m0 = blockIdx.y * 128;
    const int n0 = blockIdx.x * 128;

    float acc[4][4][4];
#pragma unroll
    for (int mt = 0; mt < 4; mt++)
#pragma unroll
        for (int nt = 0; nt < 4; nt++)
#pragma unroll
            for (int k = 0; k < 4; k++) acc[mt][nt][k] = 0.f;

    {
#pragma unroll
        for (int it = 0; it < 4; it++) {
            int chunk = it * 256 + tid;
            int row = chunk >> 3, f4 = (chunk & 7) * 4;
            cpa16(sb + (uint32_t)(row * GPAD + f4) * 4,
                  X + (size_t)(m0 + row) * EMBED + f4);
        }
#pragma unroll
        for (int it = 0; it < 4; it++) {
            int chunk = it * 256 + tid;
            int row = chunk >> 3, f4 = (chunk & 7) * 4;
            cpa16(sb + (uint32_t)(G_BS + row * GPAD + f4) * 4,
                  W + (size_t)(n0 + row) * EMBED + f4);
        }
        CPA_COMMIT();
    }

    for (int t = 0; t < EMBED / 32; t++) {
        if (t + 1 < EMBED / 32) {
            const int nb = (t + 1) & 1;
            const int k0 = (t + 1) * 32;
#pragma unroll
            for (int it = 0; it < 4; it++) {
                int chunk = it * 256 + tid;
                int row = chunk >> 3, f4 = (chunk & 7) * 4;
                cpa16(sb + (uint32_t)(nb * G_ABUF + row * GPAD + f4) * 4,
                      X + (size_t)(m0 + row) * EMBED + k0 + f4);
            }
#pragma unroll
            for (int it = 0; it < 4; it++) {
                int chunk = it * 256 + tid;
                int row = chunk >> 3, f4 = (chunk & 7) * 4;
                cpa16(sb + (uint32_t)(G_BS + nb * G_ABUF + row * GPAD + f4) * 4,
                      W + (size_t)(n0 + row) * EMBED + k0 + f4);
            }
            CPA_COMMIT();
            CPA_WAIT(1);
        } else {
            CPA_WAIT(0);
        }
        __syncthreads();

        const float* Ab = gsm + (t & 1) * G_ABUF;
        const float* Bb = gsm + G_BS + (t & 1) * G_ABUF;

#pragma unroll
        for (int ks = 0; ks < 4; ks++) {
            uint32_t af[4][4], bf[4][2];
#pragma unroll
            for (int mt = 0; mt < 4; mt++) {
                const float* ap = Ab + (wm * 64 + mt * 16 + g) * GPAD + ks * 8 + tg;
                af[mt][0] = f2tf32(ap[0]);
                af[mt][1] = f2tf32(ap[8 * GPAD]);
                af[mt][2] = f2tf32(ap[4]);
                af[mt][3] = f2tf32(ap[8 * GPAD + 4]);
            }
#pragma unroll
            for (int nt = 0; nt < 4; nt++) {
                const float* bp = Bb + (wn * 32 + nt * 8 + g) * GPAD + ks * 8 + tg;
                bf[nt][0] = f2tf32(bp[0]);
                bf[nt][1] = f2tf32(bp[4]);
            }
#pragma unroll
            for (int mt = 0; mt < 4; mt++)
#pragma unroll
                for (int nt = 0; nt < 4; nt++)
                    MMA_TF32(acc[mt][nt], af[mt], bf[nt]);
        }
        __syncthreads();
    }

#pragma unroll
    for (int mt = 0; mt < 4; mt++) {
#pragma unroll
        for (int nt = 0; nt < 4; nt++) {
            int row = m0 + wm * 64 + mt * 16 + g;
            int col = n0 + wn * 32 + nt * 8 + 2 * tg;
            float b0 = bias[col], b1 = bias[col + 1];
            qkv_scatter(acc[mt][nt][0] + b0, row,     col);
            qkv_scatter(acc[mt][nt][1] + b1, row,     col + 1);
            qkv_scatter(acc[mt][nt][2] + b0, row + 8, col);
            qkv_scatter(acc[mt][nt][3] + b1, row + 8, col + 1);
        }
    }
}

// ---------------------------------------------------------------------------
// Kernel 2: flash attention on tensor cores (tf32 mma).
// CTA = (b,h,128 q), 256 thr = 8 warps; warp = 16 q rows x full 32-key tile.
// Double-buffered cp.async K/V; warp-private P smem round-trip.
// Conflict-free strides: K 40, V 72, P 36.
// ---------------------------------------------------------------------------
#define KSTR 40
#define VSTR 72
#define PSTR 36
#define SM_K0 0
#define SM_K1 (64 * KSTR)                 // 2560
#define SM_V0 (2 * 64 * KSTR)             // 5120
#define SM_V1 (SM_V0 + 32 * VSTR)         // 7424
#define SM_P  (SM_V0 + 2 * 32 * VSTR)     // 9728
#define SM_TOTF (SM_P + 128 * PSTR)       // 14336 floats
#define ATTN_SMEM (SM_TOTF * sizeof(float))   // 57344 B

__global__ __launch_bounds__(256, 2) void attn_kernel(float* __restrict__ out)
{
    extern __shared__ float sm[];
    const uint32_t sbase = smem_u32(sm);

    const int b  = blockIdx.z;
    const int h  = blockIdx.y;
    const int m0 = blockIdx.x * 128;
    const size_t bh = (size_t)b * HEADS + h;
    const float* Qg = g_qkv + bh * SEQ * HD;                 // [n][d]
    const float* Kg = g_qkv + PER_BUF + bh * HD * SEQ;       // [d][n]
    const float* Vg = g_qkv + 2 * PER_BUF + bh * SEQ * HD;   // [n][d]

    const int tid  = threadIdx.x;
    const int lane = tid & 31;
    const int w    = tid >> 5;        // warp 0..7 -> q rows [16w, 16w+16)
    const int g    = lane >> 2;       // 0..7
    const int tg   = lane & 3;        // 0..3

    // ---- persistent Q fragments (values already tf32+scaled in gmem) ----
    uint32_t qf[8][4];
    {
        const uint32_t* Qu = (const uint32_t*)Qg;
        const size_t r0 = (size_t)(m0 + w * 16 + g) * HD;
        const size_t r1 = r0 + 8 * HD;
#pragma unroll
        for (int ks = 0; ks < 8; ks++) {
            qf[ks][0] = Qu[r0 + ks * 8 + tg];
            qf[ks][1] = Qu[r1 + ks * 8 + tg];
            qf[ks][2] = Qu[r0 + ks * 8 + tg + 4];
            qf[ks][3] = Qu[r1 + ks * 8 + tg + 4];
        }
    }

    // ---- stage KV tile 0 into buf 0 ----
#pragma unroll
    for (int it = 0; it < 2; it++) {
        int c = it * 256 + tid;                   // 0..511
        int kr = c >> 3, kf = (c & 7) * 4;        // K: 64 rows x 32
        cpa16(sbase + (uint32_t)(SM_K0 + kr * KSTR + kf) * 4,
              Kg + (size_t)kr * SEQ + kf);
        int vr = c >> 4, vf = (c & 15) * 4;       // V: 32 rows x 64
        cpa16(sbase + (uint32_t)(SM_V0 + vr * VSTR + vf) * 4,
              Vg + (size_t)vr * HD + vf);
    }
    CPA_COMMIT();

    float o[8][4];
#pragma unroll
    for (int nf = 0; nf < 8; nf++)
#pragma unroll
        for (int k = 0; k < 4; k++) o[nf][k] = 0.f;
    float m0r = -1e30f, m1r = -1e30f, l0 = 0.f, l1 = 0.f;

    uint32_t* Pu = (uint32_t*)(sm + SM_P) + w * 16 * PSTR;   // warp-private

    for (int t = 0; t < SEQ / 32; t++) {
        const int buf = t & 1;
        if (t + 1 < SEQ / 32) {
            const int n1 = (t + 1) * 32;
            const uint32_t kd = buf ? SM_K0 : SM_K1;
            const uint32_t vd = buf ? SM_V0 : SM_V1;
#pragma unroll
            for (int it = 0; it < 2; it++) {
                int c = it * 256 + tid;
                int kr = c >> 3, kf = (c & 7) * 4;
                cpa16(sbase + (kd + (uint32_t)(kr * KSTR + kf)) * 4,
                      Kg + (size_t)kr * SEQ + n1 + kf);
                int vr = c >> 4, vf = (c & 15) * 4;
                cpa16(sbase + (vd + (uint32_t)(vr * VSTR + vf)) * 4,
                      Vg + (size_t)(n1 + vr) * HD + vf);
            }
            CPA_COMMIT();
            CPA_WAIT(1);
        } else {
            CPA_WAIT(0);
        }
        __syncthreads();

        const uint32_t* Ku = (const uint32_t*)(sm + (buf ? SM_K1 : SM_K0));
        const uint32_t* Vu = (const uint32_t*)(sm + (buf ? SM_V1 : SM_V0));

        // ---- QK: S (16q x 32j per warp) via 32 mma ----
        float s[4][4];
#pragma unroll
        for (int nf = 0; nf < 4; nf++)
#pragma unroll
            for (int k = 0; k < 4; k++) s[nf][k] = 0.f;
#pragma unroll
        for (int ks = 0; ks < 8; ks++) {
#pragma unroll
            for (int nf = 0; nf < 4; nf++) {
                uint32_t bfr[2];
                bfr[0] = Ku[(ks * 8 + tg)     * KSTR + nf * 8 + g];
                bfr[1] = Ku[(ks * 8 + tg + 4) * KSTR + nf * 8 + g];
                MMA_TF32(s[nf], qf[ks], bfr);
            }
        }

        // ---- online softmax (rows g and g+8; full row lives in the quad) ----
        float mx0 = -1e30f, mx1 = -1e30f;
#pragma unroll
        for (int nf = 0; nf < 4; nf++) {
            mx0 = fmaxf(mx0, fmaxf(s[nf][0], s[nf][1]));
            mx1 = fmaxf(mx1, fmaxf(s[nf][2], s[nf][3]));
        }
        mx0 = fmaxf(mx0, __shfl_xor_sync(0xffffffffu, mx0, 1, 4));
        mx0 = fmaxf(mx0, __shfl_xor_sync(0xffffffffu, mx0, 2, 4));
        mx1 = fmaxf(mx1, __shfl_xor_sync(0xffffffffu, mx1, 1, 4));
        mx1 = fmaxf(mx1, __shfl_xor_sync(0xffffffffu, mx1, 2, 4));
        float mn0 = fmaxf(m0r, mx0), mn1 = fmaxf(m1r, mx1);
        float a0 = __expf(m0r - mn0), a1 = __expf(m1r - mn1);
        m0r = mn0; m1r = mn1;
        float sum0 = 0.f, sum1 = 0.f;
#pragma unroll
        for (int nf = 0; nf < 4; nf++) {
            s[nf][0] = __expf(s[nf][0] - mn0);
            s[nf][1] = __expf(s[nf][1] - mn0);
            s[nf][2] = __expf(s[nf][2] - mn1);
            s[nf][3] = __expf(s[nf][3] - mn1);
            sum0 += s[nf][0] + s[nf][1];
            sum1 += s[nf][2] + s[nf][3];
        }
        sum0 += __shfl_xor_sync(0xffffffffu, sum0, 1, 4);
        sum0 += __shfl_xor_sync(0xffffffffu, sum0, 2, 4);
        sum1 += __shfl_xor_sync(0xffffffffu, sum1, 1, 4);
        sum1 += __shfl_xor_sync(0xffffffffu, sum1, 2, 4);
        l0 = l0 * a0 + sum0;
        l1 = l1 * a1 + sum1;
#pragma unroll
        for (int nf = 0; nf < 8; nf++) {
            o[nf][0] *= a0; o[nf][1] *= a0;
            o[nf][2] *= a1; o[nf][3] *= a1;
        }

        // ---- store P fragments to warp-private smem (tf32 bits) ----
#pragma unroll
        for (int nf = 0; nf < 4; nf++) {
            uint2 v0 = make_uint2(f2tf32(s[nf][0]), f2tf32(s[nf][1]));
            uint2 v1 = make_uint2(f2tf32(s[nf][2]), f2tf32(s[nf][3]));
            *(uint2*)(Pu + g * PSTR + nf * 8 + 2 * tg)       = v0;
            *(uint2*)(Pu + (g + 8) * PSTR + nf * 8 + 2 * tg) = v1;
        }
        __syncwarp();

        // ---- PV: O (16q x 64d) += P (16x32) . V (32x64), 32 mma ----
#pragma unroll
        for (int ks = 0; ks < 4; ks++) {
            uint32_t pa[4];
            pa[0] = Pu[g * PSTR + ks * 8 + tg];
            pa[1] = Pu[(g + 8) * PSTR + ks * 8 + tg];
            pa[2] = Pu[g * PSTR + ks * 8 + tg + 4];
            pa[3] = Pu[(g + 8) * PSTR + ks * 8 + tg + 4];
#pragma unroll
            for (int nf = 0; nf < 8; nf++) {
                uint32_t bfr[2];
                bfr[0] = Vu[(ks * 8 + tg)     * VSTR + nf * 8 + g];
                bfr[1] = Vu[(ks * 8 + tg + 4) * VSTR + nf * 8 + g];
                MMA_TF32(o[nf], pa, bfr);
            }
        }
        __syncwarp();       // P reads done before next tile's stores
        __syncthreads();    // K/V buffer reads done before refill
    }

    // ---- epilogue ----
    float i0 = 1.f / l0, i1 = 1.f / l1;
    float* op0 = out + ((size_t)b * SEQ + m0 + w * 16 + g) * EMBED + h * HD;
    float* op1 = op0 + 8 * EMBED;
#pragma unroll
    for (int nf = 0; nf < 8; nf++) {
        float2 r0 = make_float2(o[nf][0] * i0, o[nf][1] * i0);
        float2 r1 = make_float2(o[nf][2] * i1, o[nf][3] * i1);
        *(float2*)(op0 + nf * 8 + 2 * tg) = r0;
        *(float2*)(op1 + nf * 8 + 2 * tg) = r1;
    }
}

// ---------------------------------------------------------------------------
extern "C" void kernel_launch(void* const* d_in, const int* in_sizes, int n_in,
                              void* d_out, int out_size)
{
    const float* x    = (const float*)d_in[0];
    const float* W    = (const float*)d_in[1];
    const float* bias = (const float*)d_in[2];
    float* out = (float*)d_out;

    cudaFuncSetAttribute(qkv_gemm_kernel, cudaFuncAttributeMaxDynamicSharedMemorySize,
                         (int)GEMM_SMEM);
    dim3 ggrid(THREE_E / 128, M_TOTAL / 128);    // (18, 64)
    qkv_gemm_kernel<<<ggrid, 256, GEMM_SMEM>>>(x, W, bias);

    cudaFuncSetAttribute(attn_kernel, cudaFuncAttributeMaxDynamicSharedMemorySize,
                         (int)ATTN_SMEM);
    dim3 agrid(SEQ / 128, HEADS, BATCH);         // (8, 12, 8)
    attn_kernel<<<agrid, 256, ATTN_SMEM>>>(out);
}

// round 9
// speedup vs baseline: 13.1030x; 1.0541x over previous
#include <cuda_runtime.h>
#include <math.h>
#include <stdint.h>

#define EMBED   768
#define THREE_E 2304
#define HEADS   12
#define HD      64
#define BATCH   8
#define SEQ     1024
#define M_TOTAL (BATCH * SEQ)          // 8192
#define PER_BUF ((size_t)BATCH * HEADS * SEQ * HD)

// Scratch: Q [b][h][n][d] (pre-scaled 1/8, tf32-rounded)
//          K [b][h][d][n] (tf32-rounded)
//          V [b][h][n][d] (tf32-rounded)
__device__ float g_qkv[3 * PER_BUF];
// Pre-rounded tf32 copies of X and W for the GEMM mainloop
__device__ float g_xr[(size_t)M_TOTAL * EMBED];
__device__ float g_wr[(size_t)THREE_E * EMBED];

// ---- cp.async ----
__device__ __forceinline__ uint32_t smem_u32(const void* p) {
    return (uint32_t)__cvta_generic_to_shared(p);
}
__device__ __forceinline__ void cpa16(uint32_t s, const void* g) {
    asm volatile("cp.async.cg.shared.global [%0], [%1], 16;" :: "r"(s), "l"(g));
}
#define CPA_COMMIT() asm volatile("cp.async.commit_group;")
#define CPA_WAIT(n)  asm volatile("cp.async.wait_group %0;" :: "n"(n))

// ---- tf32 ----
__device__ __forceinline__ uint32_t f2tf32(float f) {
    uint32_t r; asm("cvt.rna.tf32.f32 %0, %1;" : "=r"(r) : "f"(f)); return r;
}
#define MMA_TF32(c, a, b) \
    asm volatile("mma.sync.aligned.m16n8k8.row.col.f32.tf32.tf32.f32 " \
        "{%0,%1,%2,%3},{%4,%5,%6,%7},{%8,%9},{%0,%1,%2,%3};" \
        : "+f"((c)[0]), "+f"((c)[1]), "+f"((c)[2]), "+f"((c)[3]) \
        : "r"((a)[0]), "r"((a)[1]), "r"((a)[2]), "r"((a)[3]), \
          "r"((b)[0]), "r"((b)[1]))

// ---------------------------------------------------------------------------
// Kernel 0: pre-round X and W to tf32 (removes all cvts from GEMM mainloop)
// ---------------------------------------------------------------------------
#define XR_F4 ((size_t)M_TOTAL * EMBED / 4)    // 1,572,864
#define WR_F4 ((size_t)THREE_E * EMBED / 4)    // 442,368

__global__ __launch_bounds__(256) void preround_kernel(
    const float4* __restrict__ X, const float4* __restrict__ W)
{
    float4* xr = (float4*)g_xr;
    float4* wr = (float4*)g_wr;
    size_t i = (size_t)blockIdx.x * blockDim.x + threadIdx.x;
    size_t stride = (size_t)gridDim.x * blockDim.x;
    for (; i < XR_F4 + WR_F4; i += stride) {
        float4 v; float4* dst;
        if (i < XR_F4) { v = X[i]; dst = xr + i; }
        else           { v = W[i - XR_F4]; dst = wr + (i - XR_F4); }
        v.x = __uint_as_float(f2tf32(v.x));
        v.y = __uint_as_float(f2tf32(v.y));
        v.z = __uint_as_float(f2tf32(v.z));
        v.w = __uint_as_float(f2tf32(v.w));
        *dst = v;
    }
}

// ---------------------------------------------------------------------------
// Kernel 1: QKV projection, tf32 tensor-core GEMM, cvt-free mainloop.
// ---------------------------------------------------------------------------
#define GPAD 36
#define G_ABUF (128 * GPAD)
#define G_BS   (2 * G_ABUF)
#define GEMM_SMEM (4 * G_ABUF * sizeof(float))   // 73728 B

__device__ __forceinline__ void qkv_scatter(float val, int m, int c) {
    int bidx = m >> 10;
    int n    = m & (SEQ - 1);
    int hh = c / 192;
    int r  = c - hh * 192;
    int which = r >> 6;
    int d = r & 63;
    if (which == 0) val *= 0.125f;                 // fold 1/sqrt(64) into Q
    val = __uint_as_float(f2tf32(val));            // pre-round to tf32
    size_t idx;
    if (which == 1)   // K: [b][h][d][n]
        idx = PER_BUF + (((size_t)bidx * HEADS + hh) * HD + d) * SEQ + n;
    else              // Q (0), V (2): [b][h][n][d]
        idx = (size_t)which * PER_BUF +
              (((size_t)bidx * HEADS + hh) * SEQ + n) * HD + d;
    g_qkv[idx] = val;
}

__global__ __launch_bounds__(256, 2) void qkv_gemm_kernel(
    const float* __restrict__ bias)
{
    extern __shared__ float gsm[];
    const uint32_t sb = smem_u32(gsm);
    const float* X = g_xr;
    const float* W = g_wr;

    const int tid  = threadIdx.x;
    const int lane = tid & 31;
    const int wid  = tid >> 5;
    const int wm   = wid >> 2;
    const int wn   = wid & 3;
    const int g    = lane >> 2;
    const int tg   = lane & 3;
    const int m0 = blockIdx.y * 128;
    const int n0 = blockIdx.x * 128;

    float acc[4][4][4];
#pragma unroll
    for (int mt = 0; mt < 4; mt++)
#pragma unroll
        for (int nt = 0; nt < 4; nt++)
#pragma unroll
            for (int k = 0; k < 4; k++) acc[mt][nt][k] = 0.f;

    {
#pragma unroll
        for (int it = 0; it < 4; it++) {
            int chunk = it * 256 + tid;
            int row = chunk >> 3, f4 = (chunk & 7) * 4;
            cpa16(sb + (uint32_t)(row * GPAD + f4) * 4,
                  X + (size_t)(m0 + row) * EMBED + f4);
        }
#pragma unroll
        for (int it = 0; it < 4; it++) {
            int chunk = it * 256 + tid;
            int row = chunk >> 3, f4 = (chunk & 7) * 4;
            cpa16(sb + (uint32_t)(G_BS + row * GPAD + f4) * 4,
                  W + (size_t)(n0 + row) * EMBED + f4);
        }
        CPA_COMMIT();
    }

    for (int t = 0; t < EMBED / 32; t++) {
        if (t + 1 < EMBED / 32) {
            const int nb = (t + 1) & 1;
            const int k0 = (t + 1) * 32;
#pragma unroll
            for (int it = 0; it < 4; it++) {
                int chunk = it * 256 + tid;
                int row = chunk >> 3, f4 = (chunk & 7) * 4;
                cpa16(sb + (uint32_t)(nb * G_ABUF + row * GPAD + f4) * 4,
                      X + (size_t)(m0 + row) * EMBED + k0 + f4);
            }
#pragma unroll
            for (int it = 0; it < 4; it++) {
                int chunk = it * 256 + tid;
                int row = chunk >> 3, f4 = (chunk & 7) * 4;
                cpa16(sb + (uint32_t)(G_BS + nb * G_ABUF + row * GPAD + f4) * 4,
                      W + (size_t)(n0 + row) * EMBED + k0 + f4);
            }
            CPA_COMMIT();
            CPA_WAIT(1);
        } else {
            CPA_WAIT(0);
        }
        __syncthreads();

        const uint32_t* Ab = (const uint32_t*)(gsm + (t & 1) * G_ABUF);
        const uint32_t* Bb = (const uint32_t*)(gsm + G_BS + (t & 1) * G_ABUF);

#pragma unroll
        for (int ks = 0; ks < 4; ks++) {
            uint32_t af[4][4], bf[4][2];
#pragma unroll
            for (int mt = 0; mt < 4; mt++) {
                const uint32_t* ap = Ab + (wm * 64 + mt * 16 + g) * GPAD + ks * 8 + tg;
                af[mt][0] = ap[0];
                af[mt][1] = ap[8 * GPAD];
                af[mt][2] = ap[4];
                af[mt][3] = ap[8 * GPAD + 4];
            }
#pragma unroll
            for (int nt = 0; nt < 4; nt++) {
                const uint32_t* bp = Bb + (wn * 32 + nt * 8 + g) * GPAD + ks * 8 + tg;
                bf[nt][0] = bp[0];
                bf[nt][1] = bp[4];
            }
#pragma unroll
            for (int mt = 0; mt < 4; mt++)
#pragma unroll
                for (int nt = 0; nt < 4; nt++)
                    MMA_TF32(acc[mt][nt], af[mt], bf[nt]);
        }
        __syncthreads();
    }

#pragma unroll
    for (int mt = 0; mt < 4; mt++) {
#pragma unroll
        for (int nt = 0; nt < 4; nt++) {
            int row = m0 + wm * 64 + mt * 16 + g;
            int col = n0 + wn * 32 + nt * 8 + 2 * tg;
            float b0 = bias[col], b1 = bias[col + 1];
            qkv_scatter(acc[mt][nt][0] + b0, row,     col);
            qkv_scatter(acc[mt][nt][1] + b1, row,     col + 1);
            qkv_scatter(acc[mt][nt][2] + b0, row + 8, col);
            qkv_scatter(acc[mt][nt][3] + b1, row + 8, col + 1);
        }
    }
}

// ---------------------------------------------------------------------------
// Kernel 2: flash attention on tensor cores, 32 q-rows per warp.
// CTA = (b,h,128 q), 128 thr = 4 warps; warp = 2 stacked m16 tiles x 32 keys.
// B-fragments (K and V) amortized over 2 mma each.
// ---------------------------------------------------------------------------
#define KSTR 40
#define VSTR 72
#define PSTR 36
#define SM_K0 0
#define SM_K1 (64 * KSTR)                 // 2560
#define SM_V0 (2 * 64 * KSTR)             // 5120
#define SM_V1 (SM_V0 + 32 * VSTR)         // 7424
#define SM_P  (SM_V0 + 2 * 32 * VSTR)     // 9728
#define SM_TOTF (SM_P + 128 * PSTR)       // 14336 floats
#define ATTN_SMEM (SM_TOTF * sizeof(float))   // 57344 B

__global__ __launch_bounds__(128, 2) void attn_kernel(float* __restrict__ out)
{
    extern __shared__ float sm[];
    const uint32_t sbase = smem_u32(sm);

    const int b  = blockIdx.z;
    const int h  = blockIdx.y;
    const int m0 = blockIdx.x * 128;
    const size_t bh = (size_t)b * HEADS + h;
    const float* Qg = g_qkv + bh * SEQ * HD;                 // [n][d]
    const float* Kg = g_qkv + PER_BUF + bh * HD * SEQ;       // [d][n]
    const float* Vg = g_qkv + 2 * PER_BUF + bh * SEQ * HD;   // [n][d]

    const int tid  = threadIdx.x;
    const int lane = tid & 31;
    const int w    = tid >> 5;        // warp 0..3 -> q rows [32w, 32w+32)
    const int g    = lane >> 2;       // 0..7
    const int tg   = lane & 3;        // 0..3

    // ---- persistent Q fragments: 2 m-tiles ----
    uint32_t qf[2][8][4];
    {
        const uint32_t* Qu = (const uint32_t*)Qg;
#pragma unroll
        for (int mt = 0; mt < 2; mt++) {
            const size_t r0 = (size_t)(m0 + w * 32 + mt * 16 + g) * HD;
            const size_t r1 = r0 + 8 * HD;
#pragma unroll
            for (int ks = 0; ks < 8; ks++) {
                qf[mt][ks][0] = Qu[r0 + ks * 8 + tg];
                qf[mt][ks][1] = Qu[r1 + ks * 8 + tg];
                qf[mt][ks][2] = Qu[r0 + ks * 8 + tg + 4];
                qf[mt][ks][3] = Qu[r1 + ks * 8 + tg + 4];
            }
        }
    }

    // ---- stage KV tile 0 into buf 0 (128 threads: 4 chunks each) ----
#pragma unroll
    for (int it = 0; it < 4; it++) {
        int c = it * 128 + tid;                   // 0..511
        int kr = c >> 3, kf = (c & 7) * 4;        // K: 64 rows x 32
        cpa16(sbase + (uint32_t)(SM_K0 + kr * KSTR + kf) * 4,
              Kg + (size_t)kr * SEQ + kf);
        int vr = c >> 4, vf = (c & 15) * 4;       // V: 32 rows x 64
        cpa16(sbase + (uint32_t)(SM_V0 + vr * VSTR + vf) * 4,
              Vg + (size_t)vr * HD + vf);
    }
    CPA_COMMIT();

    float o[2][8][4];
#pragma unroll
    for (int mt = 0; mt < 2; mt++)
#pragma unroll
        for (int nf = 0; nf < 8; nf++)
#pragma unroll
            for (int k = 0; k < 4; k++) o[mt][nf][k] = 0.f;
    float m_r[2][2], l_r[2][2];
#pragma unroll
    for (int mt = 0; mt < 2; mt++) {
        m_r[mt][0] = m_r[mt][1] = -1e30f;
        l_r[mt][0] = l_r[mt][1] = 0.f;
    }

    uint32_t* Pu = (uint32_t*)(sm + SM_P) + w * 32 * PSTR;   // warp-private

    for (int t = 0; t < SEQ / 32; t++) {
        const int buf = t & 1;
        if (t + 1 < SEQ / 32) {
            const int n1 = (t + 1) * 32;
            const uint32_t kd = buf ? SM_K0 : SM_K1;
            const uint32_t vd = buf ? SM_V0 : SM_V1;
#pragma unroll
            for (int it = 0; it < 4; it++) {
                int c = it * 128 + tid;
                int kr = c >> 3, kf = (c & 7) * 4;
                cpa16(sbase + (kd + (uint32_t)(kr * KSTR + kf)) * 4,
                      Kg + (size_t)kr * SEQ + n1 + kf);
                int vr = c >> 4, vf = (c & 15) * 4;
                cpa16(sbase + (vd + (uint32_t)(vr * VSTR + vf)) * 4,
                      Vg + (size_t)(n1 + vr) * HD + vf);
            }
            CPA_COMMIT();
            CPA_WAIT(1);
        } else {
            CPA_WAIT(0);
        }
        __syncthreads();

        const uint32_t* Ku = (const uint32_t*)(sm + (buf ? SM_K1 : SM_K0));
        const uint32_t* Vu = (const uint32_t*)(sm + (buf ? SM_V1 : SM_V0));

        // ---- QK: S (2x 16q x 32j per warp), B-frag shared by both m-tiles ----
        float s[2][4][4];
#pragma unroll
        for (int mt = 0; mt < 2; mt++)
#pragma unroll
            for (int nf = 0; nf < 4; nf++)
#pragma unroll
                for (int k = 0; k < 4; k++) s[mt][nf][k] = 0.f;
#pragma unroll
        for (int ks = 0; ks < 8; ks++) {
#pragma unroll
            for (int nf = 0; nf < 4; nf++) {
                uint32_t bfr[2];
                bfr[0] = Ku[(ks * 8 + tg)     * KSTR + nf * 8 + g];
                bfr[1] = Ku[(ks * 8 + tg + 4) * KSTR + nf * 8 + g];
                MMA_TF32(s[0][nf], qf[0][ks], bfr);
                MMA_TF32(s[1][nf], qf[1][ks], bfr);
            }
        }

        // ---- online softmax per m-tile ----
#pragma unroll
        for (int mt = 0; mt < 2; mt++) {
            float mx0 = -1e30f, mx1 = -1e30f;
#pragma unroll
            for (int nf = 0; nf < 4; nf++) {
                mx0 = fmaxf(mx0, fmaxf(s[mt][nf][0], s[mt][nf][1]));
                mx1 = fmaxf(mx1, fmaxf(s[mt][nf][2], s[mt][nf][3]));
            }
            mx0 = fmaxf(mx0, __shfl_xor_sync(0xffffffffu, mx0, 1, 4));
            mx0 = fmaxf(mx0, __shfl_xor_sync(0xffffffffu, mx0, 2, 4));
            mx1 = fmaxf(mx1, __shfl_xor_sync(0xffffffffu, mx1, 1, 4));
            mx1 = fmaxf(mx1, __shfl_xor_sync(0xffffffffu, mx1, 2, 4));
            float mn0 = fmaxf(m_r[mt][0], mx0), mn1 = fmaxf(m_r[mt][1], mx1);
            float a0 = __expf(m_r[mt][0] - mn0), a1 = __expf(m_r[mt][1] - mn1);
            m_r[mt][0] = mn0; m_r[mt][1] = mn1;
            float sum0 = 0.f, sum1 = 0.f;
#pragma unroll
            for (int nf = 0; nf < 4; nf++) {
                s[mt][nf][0] = __expf(s[mt][nf][0] - mn0);
                s[mt][nf][1] = __expf(s[mt][nf][1] - mn0);
                s[mt][nf][2] = __expf(s[mt][nf][2] - mn1);
                s[mt][nf][3] = __expf(s[mt][nf][3] - mn1);
                sum0 += s[mt][nf][0] + s[mt][nf][1];
                sum1 += s[mt][nf][2] + s[mt][nf][3];
            }
            sum0 += __shfl_xor_sync(0xffffffffu, sum0, 1, 4);
            sum0 += __shfl_xor_sync(0xffffffffu, sum0, 2, 4);
            sum1 += __shfl_xor_sync(0xffffffffu, sum1, 1, 4);
            sum1 += __shfl_xor_sync(0xffffffffu, sum1, 2, 4);
            l_r[mt][0] = l_r[mt][0] * a0 + sum0;
            l_r[mt][1] = l_r[mt][1] * a1 + sum1;
#pragma unroll
            for (int nf = 0; nf < 8; nf++) {
                o[mt][nf][0] *= a0; o[mt][nf][1] *= a0;
                o[mt][nf][2] *= a1; o[mt][nf][3] *= a1;
            }

            // store P fragments (tf32 bits) to warp-private smem
#pragma unroll
            for (int nf = 0; nf < 4; nf++) {
                uint2 v0 = make_uint2(f2tf32(s[mt][nf][0]), f2tf32(s[mt][nf][1]));
                uint2 v1 = make_uint2(f2tf32(s[mt][nf][2]), f2tf32(s[mt][nf][3]));
                *(uint2*)(Pu + (mt * 16 + g) * PSTR + nf * 8 + 2 * tg)     = v0;
                *(uint2*)(Pu + (mt * 16 + 8 + g) * PSTR + nf * 8 + 2 * tg) = v1;
            }
        }
        __syncwarp();

        // ---- PV: O += P . V, B-frag shared by both m-tiles ----
#pragma unroll
        for (int ks = 0; ks < 4; ks++) {
            uint32_t pa[2][4];
#pragma unroll
            for (int mt = 0; mt < 2; mt++) {
                pa[mt][0] = Pu[(mt * 16 + g) * PSTR + ks * 8 + tg];
                pa[mt][1] = Pu[(mt * 16 + 8 + g) * PSTR + ks * 8 + tg];
                pa[mt][2] = Pu[(mt * 16 + g) * PSTR + ks * 8 + tg + 4];
                pa[mt][3] = Pu[(mt * 16 + 8 + g) * PSTR + ks * 8 + tg + 4];
            }
#pragma unroll
            for (int nf = 0; nf < 8; nf++) {
                uint32_t bfr[2];
                bfr[0] = Vu[(ks * 8 + tg)     * VSTR + nf * 8 + g];
                bfr[1] = Vu[(ks * 8 + tg + 4) * VSTR + nf * 8 + g];
                MMA_TF32(o[0][nf], pa[0], bfr);
                MMA_TF32(o[1][nf], pa[1], bfr);
            }
        }
        __syncwarp();       // P reads done before next tile's stores
        __syncthreads();    // K/V buffer reads done before refill
    }

    // ---- epilogue ----
#pragma unroll
    for (int mt = 0; mt < 2; mt++) {
        float i0 = 1.f / l_r[mt][0], i1 = 1.f / l_r[mt][1];
        float* op0 = out + ((size_t)b * SEQ + m0 + w * 32 + mt * 16 + g) * EMBED + h * HD;
        float* op1 = op0 + 8 * EMBED;
#pragma unroll
        for (int nf = 0; nf < 8; nf++) {
            float2 r0 = make_float2(o[mt][nf][0] * i0, o[mt][nf][1] * i0);
            float2 r1 = make_float2(o[mt][nf][2] * i1, o[mt][nf][3] * i1);
            *(float2*)(op0 + nf * 8 + 2 * tg) = r0;
            *(float2*)(op1 + nf * 8 + 2 * tg) = r1;
        }
    }
}

// ---------------------------------------------------------------------------
extern "C" void kernel_launch(void* const* d_in, const int* in_sizes, int n_in,
                              void* d_out, int out_size)
{
    const float* x    = (const float*)d_in[0];
    const float* W    = (const float*)d_in[1];
    const float* bias = (const float*)d_in[2];
    float* out = (float*)d_out;

    preround_kernel<<<4096, 256>>>((const float4*)x, (const float4*)W);

    cudaFuncSetAttribute(qkv_gemm_kernel, cudaFuncAttributeMaxDynamicSharedMemorySize,
                         (int)GEMM_SMEM);
    dim3 ggrid(THREE_E / 128, M_TOTAL / 128);    // (18, 64)
    qkv_gemm_kernel<<<ggrid, 256, GEMM_SMEM>>>(bias);

    cudaFuncSetAttribute(attn_kernel, cudaFuncAttributeMaxDynamicSharedMemorySize,
                         (int)ATTN_SMEM);
    dim3 agrid(SEQ / 128, HEADS, BATCH);         // (8, 12, 8)
    attn_kernel<<<agrid, 128, ATTN_SMEM>>>(out);
}

// round 11
// speedup vs baseline: 22.5667x; 1.7223x over previous
#include <cuda_runtime.h>
#include <cuda_fp16.h>
#include <math.h>
#include <stdint.h>

#define EMBED   768
#define THREE_E 2304
#define HEADS   12
#define HD      64
#define BATCH   8
#define SEQ     1024
#define M_TOTAL (BATCH * SEQ)          // 8192
#define PER_BUF ((size_t)BATCH * HEADS * SEQ * HD)

// Scratch: Q,K,V all [b][h][n][d] fp16 (Q pre-scaled by 1/8)
__device__ __half g_qkvh[3 * PER_BUF];
// fp16 copies of X and W for the GEMM
__device__ __half g_xh[(size_t)M_TOTAL * EMBED];
__device__ __half g_wh[(size_t)THREE_E * EMBED];

// ---- cp.async ----
__device__ __forceinline__ uint32_t smem_u32(const void* p) {
    return (uint32_t)__cvta_generic_to_shared(p);
}
__device__ __forceinline__ void cpa16(uint32_t s, const void* g) {
    asm volatile("cp.async.cg.shared.global [%0], [%1], 16;" :: "r"(s), "l"(g));
}
#define CPA_COMMIT() asm volatile("cp.async.commit_group;")
#define CPA_WAIT(n)  asm volatile("cp.async.wait_group %0;" :: "n"(n))

// ---- fp16 mma: D(f32) = A(f16) B(f16) + D ----
#define MMA_F16(c, a, b) \
    asm volatile("mma.sync.aligned.m16n8k16.row.col.f32.f16.f16.f32 " \
        "{%0,%1,%2,%3},{%4,%5,%6,%7},{%8,%9},{%0,%1,%2,%3};" \
        : "+f"((c)[0]), "+f"((c)[1]), "+f"((c)[2]), "+f"((c)[3]) \
        : "r"((a)[0]), "r"((a)[1]), "r"((a)[2]), "r"((a)[3]), \
          "r"((b)[0]), "r"((b)[1]))

// ldmatrix x4 transposed (b16): for V B-fragments from [j][d] row-major smem
#define LDMX4T(r0, r1, r2, r3, addr) \
    asm volatile("ldmatrix.sync.aligned.m8n8.x4.trans.shared.b16 {%0,%1,%2,%3}, [%4];" \
        : "=r"(r0), "=r"(r1), "=r"(r2), "=r"(r3) : "r"(addr))

// ---------------------------------------------------------------------------
// Kernel 0: convert X, W to fp16
// ---------------------------------------------------------------------------
#define XN2 ((size_t)M_TOTAL * EMBED / 2)   // 3,145,728 half2
#define WN2 ((size_t)THREE_E * EMBED / 2)   // 884,736

__global__ __launch_bounds__(256) void preround_kernel(
    const float2* __restrict__ X, const float2* __restrict__ W)
{
    __half2* xh = (__half2*)g_xh;
    __half2* wh = (__half2*)g_wh;
    size_t i = (size_t)blockIdx.x * blockDim.x + threadIdx.x;
    size_t stride = (size_t)gridDim.x * blockDim.x;
    for (; i < XN2 + WN2; i += stride) {
        if (i < XN2) { float2 v = X[i]; xh[i] = __floats2half2_rn(v.x, v.y); }
        else { float2 v = W[i - XN2]; wh[i - XN2] = __floats2half2_rn(v.x, v.y); }
    }
}

// ---------------------------------------------------------------------------
// Kernel 1: QKV projection, fp16 tensor-core GEMM, f32 accumulate.
// CTA 128x128, BK=32 halves, 256 thr = 8 warps (2x4), warp tile 64x32.
// smem rows: 32 halves + 8 pad = 40 halves (20 words; 20g+tg distinct mod 32).
// ---------------------------------------------------------------------------
#define AH 40                          // halves per smem row
#define AWD 20                         // words per smem row
#define ABUF (128 * AH)                // 5120 halves per buffer
#define GEMM_SMEM (4 * ABUF * 2)       // 40960 B

__device__ __forceinline__ void qkv_scatter_h2(float v0, float v1, int m, int c) {
    int bidx = m >> 10;
    int n    = m & (SEQ - 1);
    int hh = c / 192;
    int r  = c - hh * 192;
    int which = r >> 6;
    int d = r & 63;                    // even (c = ... + 2*tg)
    if (which == 0) { v0 *= 0.125f; v1 *= 0.125f; }   // fold 1/sqrt(64) into Q
    size_t idx = (size_t)which * PER_BUF +
                 (((size_t)bidx * HEADS + hh) * SEQ + n) * HD + d;
    *(__half2*)(g_qkvh + idx) = __floats2half2_rn(v0, v1);
}

__global__ __launch_bounds__(256, 2) void qkv_gemm_kernel(
    const float* __restrict__ bias)
{
    extern __shared__ __half gsm[];
    const uint32_t sb = smem_u32(gsm);

    const int tid  = threadIdx.x;
    const int lane = tid & 31;
    const int wid  = tid >> 5;
    const int wm   = wid >> 2;
    const int wn   = wid & 3;
    const int g    = lane >> 2;
    const int tg   = lane & 3;
    const int m0 = blockIdx.y * 128;
    const int n0 = blockIdx.x * 128;

    float acc[4][4][4];
#pragma unroll
    for (int mt = 0; mt < 4; mt++)
#pragma unroll
        for (int nt = 0; nt < 4; nt++)
#pragma unroll
            for (int k = 0; k < 4; k++) acc[mt][nt][k] = 0.f;

    // stage k-block 0 into buf 0: per matrix 128 rows x 32 halves (4 chunks/row)
    {
#pragma unroll
        for (int it = 0; it < 2; it++) {
            int c = it * 256 + tid;               // 0..511
            int row = c >> 2, hc = (c & 3) * 8;
            cpa16(sb + (uint32_t)(row * AH + hc) * 2,
                  g_xh + (size_t)(m0 + row) * EMBED + hc);
            cpa16(sb + (uint32_t)(2 * ABUF + row * AH + hc) * 2,
                  g_wh + (size_t)(n0 + row) * EMBED + hc);
        }
        CPA_COMMIT();
    }

    for (int t = 0; t < EMBED / 32; t++) {
        if (t + 1 < EMBED / 32) {
            const int nb = (t + 1) & 1;
            const int k0 = (t + 1) * 32;
#pragma unroll
            for (int it = 0; it < 2; it++) {
                int c = it * 256 + tid;
                int row = c >> 2, hc = (c & 3) * 8;
                cpa16(sb + (uint32_t)(nb * ABUF + row * AH + hc) * 2,
                      g_xh + (size_t)(m0 + row) * EMBED + k0 + hc);
                cpa16(sb + (uint32_t)((2 + nb) * ABUF + row * AH + hc) * 2,
                      g_wh + (size_t)(n0 + row) * EMBED + k0 + hc);
            }
            CPA_COMMIT();
            CPA_WAIT(1);
        } else {
            CPA_WAIT(0);
        }
        __syncthreads();

        const uint32_t* Ab = (const uint32_t*)(gsm + (t & 1) * ABUF);
        const uint32_t* Bb = (const uint32_t*)(gsm + (2 + (t & 1)) * ABUF);

#pragma unroll
        for (int ks = 0; ks < 2; ks++) {          // k = ks*16 halves
            uint32_t af[4][4], bf[4][2];
#pragma unroll
            for (int mt = 0; mt < 4; mt++) {
                const uint32_t* ap = Ab + (wm * 64 + mt * 16 + g) * AWD + ks * 8 + tg;
                af[mt][0] = ap[0];
                af[mt][1] = ap[8 * AWD];
                af[mt][2] = ap[4];
                af[mt][3] = ap[8 * AWD + 4];
            }
#pragma unroll
            for (int nt = 0; nt < 4; nt++) {
                const uint32_t* bp = Bb + (wn * 32 + nt * 8 + g) * AWD + ks * 8 + tg;
                bf[nt][0] = bp[0];
                bf[nt][1] = bp[4];
            }
#pragma unroll
            for (int mt = 0; mt < 4; mt++)
#pragma unroll
                for (int nt = 0; nt < 4; nt++)
                    MMA_F16(acc[mt][nt], af[mt], bf[nt]);
        }
        __syncthreads();
    }

#pragma unroll
    for (int mt = 0; mt < 4; mt++) {
#pragma unroll
        for (int nt = 0; nt < 4; nt++) {
            int row = m0 + wm * 64 + mt * 16 + g;
            int col = n0 + wn * 32 + nt * 8 + 2 * tg;
            float b0 = bias[col], b1 = bias[col + 1];
            qkv_scatter_h2(acc[mt][nt][0] + b0, acc[mt][nt][1] + b1, row,     col);
            qkv_scatter_h2(acc[mt][nt][2] + b0, acc[mt][nt][3] + b1, row + 8, col);
        }
    }
}

// ---------------------------------------------------------------------------
// Kernel 2: flash attention, fp16 mma, BN=64 key tiles.
// CTA = (b,h,128 q), 128 thr = 4 warps; warp = 32 q rows (2 m16 tiles).
// K/V tiles [64 j][72 halves] double-buffered; P [128 q][72 halves].
// V B-fragments via ldmatrix.x4.trans (j-transpose).
// ---------------------------------------------------------------------------
#define KH   72                        // halves per tile row
#define KWD  36                        // words per tile row
#define H_K0 0
#define H_K1 (64 * KH)                 // 4608
#define H_V0 (2 * 64 * KH)             // 9216
#define H_V1 (3 * 64 * KH)             // 13824
#define H_P  (4 * 64 * KH)             // 18432
#define ATTN_SMEM ((H_P + 128 * KH) * 2)   // 55296 B

__global__ __launch_bounds__(128, 2) void attn_kernel(float* __restrict__ out)
{
    extern __shared__ __half smh[];
    const uint32_t sbase = smem_u32(smh);

    const int b  = blockIdx.z;
    const int h  = blockIdx.y;
    const int m0 = blockIdx.x * 128;
    const size_t bh = (size_t)b * HEADS + h;
    const __half* Qh = g_qkvh + bh * SEQ * HD;
    const __half* Kh = g_qkvh + PER_BUF + bh * SEQ * HD;
    const __half* Vh = g_qkvh + 2 * PER_BUF + bh * SEQ * HD;

    const int tid  = threadIdx.x;
    const int lane = tid & 31;
    const int w    = tid >> 5;        // warp -> q rows [32w, 32w+32)
    const int g    = lane >> 2;
    const int tg   = lane & 3;

    // ---- persistent Q fragments (fp16, pre-scaled): [n][32 words] gmem ----
    uint32_t qf[2][4][4];
    {
        const uint32_t* Qu = (const uint32_t*)Qh;
#pragma unroll
        for (int mt = 0; mt < 2; mt++) {
            const size_t r0 = (size_t)(m0 + w * 32 + mt * 16 + g) * (HD / 2);
#pragma unroll
            for (int ks = 0; ks < 4; ks++) {      // k = ks*16 halves
                qf[mt][ks][0] = Qu[r0 + ks * 8 + tg];
                qf[mt][ks][1] = Qu[r0 + 8 * (HD / 2) + ks * 8 + tg];
                qf[mt][ks][2] = Qu[r0 + ks * 8 + tg + 4];
                qf[mt][ks][3] = Qu[r0 + 8 * (HD / 2) + ks * 8 + tg + 4];
            }
        }
    }

    // ---- stage KV tile 0 into buf 0 (64 rows x 128B each = 512 chunks each) ----
#pragma unroll
    for (int it = 0; it < 4; it++) {
        int c = it * 128 + tid;                   // 0..511
        int row = c >> 3, hc = (c & 7) * 8;
        cpa16(sbase + (uint32_t)(H_K0 + row * KH + hc) * 2,
              Kh + (size_t)row * HD + hc);
        cpa16(sbase + (uint32_t)(H_V0 + row * KH + hc) * 2,
              Vh + (size_t)row * HD + hc);
    }
    CPA_COMMIT();

    float o[2][8][4];
#pragma unroll
    for (int mt = 0; mt < 2; mt++)
#pragma unroll
        for (int nf = 0; nf < 8; nf++)
#pragma unroll
            for (int k = 0; k < 4; k++) o[mt][nf][k] = 0.f;
    float m_r[2][2], l_r[2][2];
#pragma unroll
    for (int mt = 0; mt < 2; mt++) {
        m_r[mt][0] = m_r[mt][1] = -1e30f;
        l_r[mt][0] = l_r[mt][1] = 0.f;
    }

    uint32_t* Pu = (uint32_t*)(smh + H_P) + w * 32 * KWD;   // warp-private rows

    for (int t = 0; t < SEQ / 64; t++) {
        const int buf = t & 1;
        if (t + 1 < SEQ / 64) {
            const int n1 = (t + 1) * 64;
            const uint32_t kd = buf ? H_K0 : H_K1;
            const uint32_t vd = buf ? H_V0 : H_V1;
#pragma unroll
            for (int it = 0; it < 4; it++) {
                int c = it * 128 + tid;
                int row = c >> 3, hc = (c & 7) * 8;
                cpa16(sbase + (kd + (uint32_t)(row * KH + hc)) * 2,
                      Kh + (size_t)(n1 + row) * HD + hc);
                cpa16(sbase + (vd + (uint32_t)(row * KH + hc)) * 2,
                      Vh + (size_t)(n1 + row) * HD + hc);
            }
            CPA_COMMIT();
            CPA_WAIT(1);
        } else {
            CPA_WAIT(0);
        }
        __syncthreads();

        const uint32_t* Ku = (const uint32_t*)(smh + (buf ? H_K1 : H_K0));
        const uint32_t vhalf = buf ? H_V1 : H_V0;

        // ---- QK: S (2x 16q x 64j) ; B-frag from K [j][d] (pairs along d) ----
        float s[2][8][4];
#pragma unroll
        for (int mt = 0; mt < 2; mt++)
#pragma unroll
            for (int nf = 0; nf < 8; nf++)
#pragma unroll
                for (int k = 0; k < 4; k++) s[mt][nf][k] = 0.f;
#pragma unroll
        for (int ks = 0; ks < 4; ks++) {
#pragma unroll
            for (int nf = 0; nf < 8; nf++) {
                uint32_t bfr[2];
                const uint32_t* bp = Ku + (nf * 8 + g) * KWD + ks * 8 + tg;
                bfr[0] = bp[0];
                bfr[1] = bp[4];
                MMA_F16(s[0][nf], qf[0][ks], bfr);
                MMA_F16(s[1][nf], qf[1][ks], bfr);
            }
        }

        // ---- online softmax per m-tile, then P -> warp-private smem (fp16) ----
#pragma unroll
        for (int mt = 0; mt < 2; mt++) {
            float mx0 = -1e30f, mx1 = -1e30f;
#pragma unroll
            for (int nf = 0; nf < 8; nf++) {
                mx0 = fmaxf(mx0, fmaxf(s[mt][nf][0], s[mt][nf][1]));
                mx1 = fmaxf(mx1, fmaxf(s[mt][nf][2], s[mt][nf][3]));
            }
            mx0 = fmaxf(mx0, __shfl_xor_sync(0xffffffffu, mx0, 1, 4));
            mx0 = fmaxf(mx0, __shfl_xor_sync(0xffffffffu, mx0, 2, 4));
            mx1 = fmaxf(mx1, __shfl_xor_sync(0xffffffffu, mx1, 1, 4));
            mx1 = fmaxf(mx1, __shfl_xor_sync(0xffffffffu, mx1, 2, 4));
            float mn0 = fmaxf(m_r[mt][0], mx0), mn1 = fmaxf(m_r[mt][1], mx1);
            float a0 = __expf(m_r[mt][0] - mn0), a1 = __expf(m_r[mt][1] - mn1);
            m_r[mt][0] = mn0; m_r[mt][1] = mn1;
            float sum0 = 0.f, sum1 = 0.f;
#pragma unroll
            for (int nf = 0; nf < 8; nf++) {
                s[mt][nf][0] = __expf(s[mt][nf][0] - mn0);
                s[mt][nf][1] = __expf(s[mt][nf][1] - mn0);
                s[mt][nf][2] = __expf(s[mt][nf][2] - mn1);
                s[mt][nf][3] = __expf(s[mt][nf][3] - mn1);
                sum0 += s[mt][nf][0] + s[mt][nf][1];
                sum1 += s[mt][nf][2] + s[mt][nf][3];
            }
            sum0 += __shfl_xor_sync(0xffffffffu, sum0, 1, 4);
            sum0 += __shfl_xor_sync(0xffffffffu, sum0, 2, 4);
            sum1 += __shfl_xor_sync(0xffffffffu, sum1, 1, 4);
            sum1 += __shfl_xor_sync(0xffffffffu, sum1, 2, 4);
            l_r[mt][0] = l_r[mt][0] * a0 + sum0;
            l_r[mt][1] = l_r[mt][1] * a1 + sum1;
#pragma unroll
            for (int nf = 0; nf < 8; nf++) {
                o[mt][nf][0] *= a0; o[mt][nf][1] *= a0;
                o[mt][nf][2] *= a1; o[mt][nf][3] *= a1;
            }
            // store P rows (q = mt*16+g and +8), halves j = nf*8 + 2tg
#pragma unroll
            for (int nf = 0; nf < 8; nf++) {
                __half2 h0 = __floats2half2_rn(s[mt][nf][0], s[mt][nf][1]);
                __half2 h1 = __floats2half2_rn(s[mt][nf][2], s[mt][nf][3]);
                Pu[(mt * 16 + g) * KWD + nf * 4 + tg]     = *(uint32_t*)&h0;
                Pu[(mt * 16 + 8 + g) * KWD + nf * 4 + tg] = *(uint32_t*)&h1;
            }
        }
        __syncwarp();

        // ---- PV: O (2x 16q x 64d) += P(16x64) . V(64x64) ----
#pragma unroll
        for (int ks = 0; ks < 4; ks++) {          // j0 = ks*16
            uint32_t pa[2][4];
#pragma unroll
            for (int mt = 0; mt < 2; mt++) {
                const uint32_t* pp = Pu + (mt * 16 + g) * KWD + ks * 8 + tg;
                pa[mt][0] = pp[0];
                pa[mt][1] = pp[8 * KWD];
                pa[mt][2] = pp[4];
                pa[mt][3] = pp[8 * KWD + 4];
            }
#pragma unroll
            for (int nfp = 0; nfp < 4; nfp++) {   // d0 = nfp*16
                int vrow = ks * 16 + (lane & 15);
                int vcol = nfp * 16 + (lane >> 4) * 8;
                uint32_t addr = sbase + (vhalf + (uint32_t)(vrow * KH + vcol)) * 2;
                uint32_t v0, v1, v2, v3;
                LDMX4T(v0, v1, v2, v3, addr);
                uint32_t bA[2] = {v0, v1};
                uint32_t bB[2] = {v2, v3};
                MMA_F16(o[0][2 * nfp],     pa[0], bA);
                MMA_F16(o[1][2 * nfp],     pa[1], bA);
                MMA_F16(o[0][2 * nfp + 1], pa[0], bB);
                MMA_F16(o[1][2 * nfp + 1], pa[1], bB);
            }
        }
        __syncwarp();       // P reads done before next tile's stores
        __syncthreads();    // K/V buffer reads done before refill
    }

    // ---- epilogue (f32 out) ----
#pragma unroll
    for (int mt = 0; mt < 2; mt++) {
        float i0 = 1.f / l_r[mt][0], i1 = 1.f / l_r[mt][1];
        float* op0 = out + ((size_t)b * SEQ + m0 + w * 32 + mt * 16 + g) * EMBED + h * HD;
        float* op1 = op0 + 8 * EMBED;
#pragma unroll
        for (int nf = 0; nf < 8; nf++) {
            float2 r0 = make_float2(o[mt][nf][0] * i0, o[mt][nf][1] * i0);
            float2 r1 = make_float2(o[mt][nf][2] * i1, o[mt][nf][3] * i1);
            *(float2*)(op0 + nf * 8 + 2 * tg) = r0;
            *(float2*)(op1 + nf * 8 + 2 * tg) = r1;
        }
    }
}

// ---------------------------------------------------------------------------
extern "C" void kernel_launch(void* const* d_in, const int* in_sizes, int n_in,
                              void* d_out, int out_size)
{
    const float* x    = (const float*)d_in[0];
    const float* W    = (const float*)d_in[1];
    const float* bias = (const float*)d_in[2];
    float* out = (float*)d_out;

    preround_kernel<<<2048, 256>>>((const float2*)x, (const float2*)W);

    cudaFuncSetAttribute(qkv_gemm_kernel, cudaFuncAttributeMaxDynamicSharedMemorySize,
                         (int)GEMM_SMEM);
    dim3 ggrid(THREE_E / 128, M_TOTAL / 128);    // (18, 64)
    qkv_gemm_kernel<<<ggrid, 256, GEMM_SMEM>>>(bias);

    cudaFuncSetAttribute(attn_kernel, cudaFuncAttributeMaxDynamicSharedMemorySize,
                         (int)ATTN_SMEM);
    dim3 agrid(SEQ / 128, HEADS, BATCH);         // (8, 12, 8)
    attn_kernel<<<agrid, 128, ATTN_SMEM>>>(out);
}

// round 12
// speedup vs baseline: 26.3086x; 1.1658x over previous
#include <cuda_runtime.h>
#include <cuda_fp16.h>
#include <math.h>
#include <stdint.h>

#define EMBED   768
#define THREE_E 2304
#define HEADS   12
#define HD      64
#define BATCH   8
#define SEQ     1024
#define M_TOTAL (BATCH * SEQ)          // 8192
#define PER_BUF ((size_t)BATCH * HEADS * SEQ * HD)
#define LOG2E   1.44269504088896340736f

// Scratch: Q,K,V all [b][h][n][d] fp16 (Q pre-scaled by 0.125*log2e)
__device__ __half g_qkvh[3 * PER_BUF];
__device__ __half g_xh[(size_t)M_TOTAL * EMBED];
__device__ __half g_wh[(size_t)THREE_E * EMBED];

// ---- cp.async ----
__device__ __forceinline__ uint32_t smem_u32(const void* p) {
    return (uint32_t)__cvta_generic_to_shared(p);
}
__device__ __forceinline__ void cpa16(uint32_t s, const void* g) {
    asm volatile("cp.async.cg.shared.global [%0], [%1], 16;" :: "r"(s), "l"(g));
}
#define CPA_COMMIT() asm volatile("cp.async.commit_group;")
#define CPA_WAIT(n)  asm volatile("cp.async.wait_group %0;" :: "n"(n))

// ---- fp16 mma ----
#define MMA_F16(c, a, b) \
    asm volatile("mma.sync.aligned.m16n8k16.row.col.f32.f16.f16.f32 " \
        "{%0,%1,%2,%3},{%4,%5,%6,%7},{%8,%9},{%0,%1,%2,%3};" \
        : "+f"((c)[0]), "+f"((c)[1]), "+f"((c)[2]), "+f"((c)[3]) \
        : "r"((a)[0]), "r"((a)[1]), "r"((a)[2]), "r"((a)[3]), \
          "r"((b)[0]), "r"((b)[1]))

#define LDMX4(r0, r1, r2, r3, addr) \
    asm volatile("ldmatrix.sync.aligned.m8n8.x4.shared.b16 {%0,%1,%2,%3}, [%4];" \
        : "=r"(r0), "=r"(r1), "=r"(r2), "=r"(r3) : "r"(addr))
#define LDMX4T(r0, r1, r2, r3, addr) \
    asm volatile("ldmatrix.sync.aligned.m8n8.x4.trans.shared.b16 {%0,%1,%2,%3}, [%4];" \
        : "=r"(r0), "=r"(r1), "=r"(r2), "=r"(r3) : "r"(addr))

__device__ __forceinline__ float ex2f(float x) {
    float r; asm("ex2.approx.f32 %0, %1;" : "=f"(r) : "f"(x)); return r;
}

// ---------------------------------------------------------------------------
// Kernel 0: convert X, W to fp16
// ---------------------------------------------------------------------------
#define XN2 ((size_t)M_TOTAL * EMBED / 2)
#define WN2 ((size_t)THREE_E * EMBED / 2)

__global__ __launch_bounds__(256) void preround_kernel(
    const float2* __restrict__ X, const float2* __restrict__ W)
{
    __half2* xh = (__half2*)g_xh;
    __half2* wh = (__half2*)g_wh;
    size_t i = (size_t)blockIdx.x * blockDim.x + threadIdx.x;
    size_t stride = (size_t)gridDim.x * blockDim.x;
    for (; i < XN2 + WN2; i += stride) {
        if (i < XN2) { float2 v = X[i]; xh[i] = __floats2half2_rn(v.x, v.y); }
        else { float2 v = W[i - XN2]; wh[i - XN2] = __floats2half2_rn(v.x, v.y); }
    }
}

// ---------------------------------------------------------------------------
// Kernel 1: QKV projection, fp16 mma GEMM, ldmatrix fragment loads.
// CTA 128x128, BK=32 halves, 256 thr = 8 warps (2x4), warp tile 64x32.
// smem rows: 40 halves (80B; 5r mod 8 distinct -> ldmatrix conflict-free).
// ---------------------------------------------------------------------------
#define AH 40
#define ABUF (128 * AH)
#define GEMM_SMEM (4 * ABUF * 2)       // 40960 B

__device__ __forceinline__ void qkv_scatter_h2(float v0, float v1, int m, int c) {
    int bidx = m >> 10;
    int n    = m & (SEQ - 1);
    int hh = c / 192;
    int r  = c - hh * 192;
    int which = r >> 6;
    int d = r & 63;
    if (which == 0) { v0 *= 0.125f * LOG2E; v1 *= 0.125f * LOG2E; }
    size_t idx = (size_t)which * PER_BUF +
                 (((size_t)bidx * HEADS + hh) * SEQ + n) * HD + d;
    *(__half2*)(g_qkvh + idx) = __floats2half2_rn(v0, v1);
}

__global__ __launch_bounds__(256, 2) void qkv_gemm_kernel(
    const float* __restrict__ bias)
{
    extern __shared__ __half gsm[];
    const uint32_t sb = smem_u32(gsm);

    const int tid  = threadIdx.x;
    const int lane = tid & 31;
    const int wid  = tid >> 5;
    const int wm   = wid >> 2;
    const int wn   = wid & 3;
    const int g    = lane >> 2;
    const int tg   = lane & 3;
    const int m0 = blockIdx.y * 128;
    const int n0 = blockIdx.x * 128;

    // ldmatrix per-lane row/col selectors
    const int arow = (lane & 7) | (((lane >> 3) & 1) << 3);   // A/P pattern
    const int ak8  = ((lane >> 4) & 1) << 3;
    const int brow = ((lane >> 4) << 3) | (lane & 7);          // B pattern
    const int bk8  = ((lane >> 3) & 1) << 3;

    float acc[4][4][4];
#pragma unroll
    for (int mt = 0; mt < 4; mt++)
#pragma unroll
        for (int nt = 0; nt < 4; nt++)
#pragma unroll
            for (int k = 0; k < 4; k++) acc[mt][nt][k] = 0.f;

    {
#pragma unroll
        for (int it = 0; it < 2; it++) {
            int c = it * 256 + tid;
            int row = c >> 2, hc = (c & 3) * 8;
            cpa16(sb + (uint32_t)(row * AH + hc) * 2,
                  g_xh + (size_t)(m0 + row) * EMBED + hc);
            cpa16(sb + (uint32_t)(2 * ABUF + row * AH + hc) * 2,
                  g_wh + (size_t)(n0 + row) * EMBED + hc);
        }
        CPA_COMMIT();
    }

    for (int t = 0; t < EMBED / 32; t++) {
        if (t + 1 < EMBED / 32) {
            const int nb = (t + 1) & 1;
            const int k0 = (t + 1) * 32;
#pragma unroll
            for (int it = 0; it < 2; it++) {
                int c = it * 256 + tid;
                int row = c >> 2, hc = (c & 3) * 8;
                cpa16(sb + (uint32_t)(nb * ABUF + row * AH + hc) * 2,
                      g_xh + (size_t)(m0 + row) * EMBED + k0 + hc);
                cpa16(sb + (uint32_t)((2 + nb) * ABUF + row * AH + hc) * 2,
                      g_wh + (size_t)(n0 + row) * EMBED + k0 + hc);
            }
            CPA_COMMIT();
            CPA_WAIT(1);
        } else {
            CPA_WAIT(0);
        }
        __syncthreads();

        const uint32_t abase = sb + (uint32_t)((t & 1) * ABUF) * 2;
        const uint32_t bbase = sb + (uint32_t)((2 + (t & 1)) * ABUF) * 2;

#pragma unroll
        for (int ks = 0; ks < 2; ks++) {
            uint32_t af[4][4], bf[4][2];
#pragma unroll
            for (int mt = 0; mt < 4; mt++) {
                uint32_t addr = abase +
                    (uint32_t)((wm * 64 + mt * 16 + arow) * AH + ks * 16 + ak8) * 2;
                LDMX4(af[mt][0], af[mt][1], af[mt][2], af[mt][3], addr);
            }
#pragma unroll
            for (int p = 0; p < 2; p++) {
                uint32_t addr = bbase +
                    (uint32_t)((wn * 32 + p * 16 + brow) * AH + ks * 16 + bk8) * 2;
                uint32_t r0, r1, r2, r3;
                LDMX4(r0, r1, r2, r3, addr);
                bf[2 * p][0] = r0; bf[2 * p][1] = r1;
                bf[2 * p + 1][0] = r2; bf[2 * p + 1][1] = r3;
            }
#pragma unroll
            for (int mt = 0; mt < 4; mt++)
#pragma unroll
                for (int nt = 0; nt < 4; nt++)
                    MMA_F16(acc[mt][nt], af[mt], bf[nt]);
        }
        __syncthreads();
    }

#pragma unroll
    for (int mt = 0; mt < 4; mt++) {
#pragma unroll
        for (int nt = 0; nt < 4; nt++) {
            int row = m0 + wm * 64 + mt * 16 + g;
            int col = n0 + wn * 32 + nt * 8 + 2 * tg;
            float b0 = bias[col], b1 = bias[col + 1];
            qkv_scatter_h2(acc[mt][nt][0] + b0, acc[mt][nt][1] + b1, row,     col);
            qkv_scatter_h2(acc[mt][nt][2] + b0, acc[mt][nt][3] + b1, row + 8, col);
        }
    }
}

// ---------------------------------------------------------------------------
// Kernel 2: flash attention, fp16 mma, BN=64 tiles, ldmatrix fragments.
// CTA = (b,h,128 q), 128 thr = 4 warps; warp = 32 q rows (2 m16 tiles).
// ---------------------------------------------------------------------------
#define KH   72
#define KWD  36
#define H_K0 0
#define H_K1 (64 * KH)
#define H_V0 (2 * 64 * KH)
#define H_V1 (3 * 64 * KH)
#define H_P  (4 * 64 * KH)
#define ATTN_SMEM ((H_P + 128 * KH) * 2)   // 55296 B

__global__ __launch_bounds__(128, 2) void attn_kernel(float* __restrict__ out)
{
    extern __shared__ __half smh[];
    const uint32_t sbase = smem_u32(smh);

    const int b  = blockIdx.z;
    const int h  = blockIdx.y;
    const int m0 = blockIdx.x * 128;
    const size_t bh = (size_t)b * HEADS + h;
    const __half* Qh = g_qkvh + bh * SEQ * HD;
    const __half* Kh = g_qkvh + PER_BUF + bh * SEQ * HD;
    const __half* Vh = g_qkvh + 2 * PER_BUF + bh * SEQ * HD;

    const int tid  = threadIdx.x;
    const int lane = tid & 31;
    const int w    = tid >> 5;
    const int g    = lane >> 2;
    const int tg   = lane & 3;

    // ldmatrix per-lane selectors
    const int arow = (lane & 7) | (((lane >> 3) & 1) << 3);   // A-frag pattern
    const int ak8  = ((lane >> 4) & 1) << 3;
    const int brow = ((lane >> 4) << 3) | (lane & 7);          // B-frag pattern
    const int bk8  = ((lane >> 3) & 1) << 3;

    // ---- persistent Q fragments ----
    uint32_t qf[2][4][4];
    {
        const uint32_t* Qu = (const uint32_t*)Qh;
#pragma unroll
        for (int mt = 0; mt < 2; mt++) {
            const size_t r0 = (size_t)(m0 + w * 32 + mt * 16 + g) * (HD / 2);
#pragma unroll
            for (int ks = 0; ks < 4; ks++) {
                qf[mt][ks][0] = Qu[r0 + ks * 8 + tg];
                qf[mt][ks][1] = Qu[r0 + 8 * (HD / 2) + ks * 8 + tg];
                qf[mt][ks][2] = Qu[r0 + ks * 8 + tg + 4];
                qf[mt][ks][3] = Qu[r0 + 8 * (HD / 2) + ks * 8 + tg + 4];
            }
        }
    }

    // ---- stage KV tile 0 ----
#pragma unroll
    for (int it = 0; it < 4; it++) {
        int c = it * 128 + tid;
        int row = c >> 3, hc = (c & 7) * 8;
        cpa16(sbase + (uint32_t)(H_K0 + row * KH + hc) * 2,
              Kh + (size_t)row * HD + hc);
        cpa16(sbase + (uint32_t)(H_V0 + row * KH + hc) * 2,
              Vh + (size_t)row * HD + hc);
    }
    CPA_COMMIT();

    float o[2][8][4];
#pragma unroll
    for (int mt = 0; mt < 2; mt++)
#pragma unroll
        for (int nf = 0; nf < 8; nf++)
#pragma unroll
            for (int k = 0; k < 4; k++) o[mt][nf][k] = 0.f;
    float m_r[2][2], l_r[2][2];
#pragma unroll
    for (int mt = 0; mt < 2; mt++) {
        m_r[mt][0] = m_r[mt][1] = -1e30f;
        l_r[mt][0] = l_r[mt][1] = 0.f;
    }

    uint32_t* Pu = (uint32_t*)(smh + H_P) + w * 32 * KWD;

    for (int t = 0; t < SEQ / 64; t++) {
        const int buf = t & 1;
        if (t + 1 < SEQ / 64) {
            const int n1 = (t + 1) * 64;
            const uint32_t kd = buf ? H_K0 : H_K1;
            const uint32_t vd = buf ? H_V0 : H_V1;
#pragma unroll
            for (int it = 0; it < 4; it++) {
                int c = it * 128 + tid;
                int row = c >> 3, hc = (c & 7) * 8;
                cpa16(sbase + (kd + (uint32_t)(row * KH + hc)) * 2,
                      Kh + (size_t)(n1 + row) * HD + hc);
                cpa16(sbase + (vd + (uint32_t)(row * KH + hc)) * 2,
                      Vh + (size_t)(n1 + row) * HD + hc);
            }
            CPA_COMMIT();
            CPA_WAIT(1);
        } else {
            CPA_WAIT(0);
        }
        __syncthreads();

        const uint32_t kbase = sbase + (uint32_t)(buf ? H_K1 : H_K0) * 2;
        const uint32_t vbase = sbase + (uint32_t)(buf ? H_V1 : H_V0) * 2;

        // ---- QK: S (2x 16q x 64j); K B-frags via ldmatrix.x4 (2 nf per) ----
        float s[2][8][4];
#pragma unroll
        for (int mt = 0; mt < 2; mt++)
#pragma unroll
            for (int nf = 0; nf < 8; nf++)
#pragma unroll
                for (int k = 0; k < 4; k++) s[mt][nf][k] = 0.f;
#pragma unroll
        for (int ks = 0; ks < 4; ks++) {
#pragma unroll
            for (int p = 0; p < 4; p++) {         // nf pair = 2p, 2p+1
                uint32_t addr = kbase +
                    (uint32_t)((p * 16 + brow) * KH + ks * 16 + bk8) * 2;
                uint32_t r0, r1, r2, r3;
                LDMX4(r0, r1, r2, r3, addr);
                uint32_t bA[2] = {r0, r1};
                uint32_t bB[2] = {r2, r3};
                MMA_F16(s[0][2 * p],     qf[0][ks], bA);
                MMA_F16(s[1][2 * p],     qf[1][ks], bA);
                MMA_F16(s[0][2 * p + 1], qf[0][ks], bB);
                MMA_F16(s[1][2 * p + 1], qf[1][ks], bB);
            }
        }

        // ---- online softmax (log2 domain; Q pre-scaled by log2e/8) ----
#pragma unroll
        for (int mt = 0; mt < 2; mt++) {
            float mx0 = -1e30f, mx1 = -1e30f;
#pragma unroll
            for (int nf = 0; nf < 8; nf++) {
                mx0 = fmaxf(mx0, fmaxf(s[mt][nf][0], s[mt][nf][1]));
                mx1 = fmaxf(mx1, fmaxf(s[mt][nf][2], s[mt][nf][3]));
            }
            mx0 = fmaxf(mx0, __shfl_xor_sync(0xffffffffu, mx0, 1, 4));
            mx0 = fmaxf(mx0, __shfl_xor_sync(0xffffffffu, mx0, 2, 4));
            mx1 = fmaxf(mx1, __shfl_xor_sync(0xffffffffu, mx1, 1, 4));
            mx1 = fmaxf(mx1, __shfl_xor_sync(0xffffffffu, mx1, 2, 4));
            float mn0 = fmaxf(m_r[mt][0], mx0), mn1 = fmaxf(m_r[mt][1], mx1);
            float a0 = ex2f(m_r[mt][0] - mn0), a1 = ex2f(m_r[mt][1] - mn1);
            m_r[mt][0] = mn0; m_r[mt][1] = mn1;
            float sum0 = 0.f, sum1 = 0.f;
#pragma unroll
            for (int nf = 0; nf < 8; nf++) {
                s[mt][nf][0] = ex2f(s[mt][nf][0] - mn0);
                s[mt][nf][1] = ex2f(s[mt][nf][1] - mn0);
                s[mt][nf][2] = ex2f(s[mt][nf][2] - mn1);
                s[mt][nf][3] = ex2f(s[mt][nf][3] - mn1);
                sum0 += s[mt][nf][0] + s[mt][nf][1];
                sum1 += s[mt][nf][2] + s[mt][nf][3];
            }
            sum0 += __shfl_xor_sync(0xffffffffu, sum0, 1, 4);
            sum0 += __shfl_xor_sync(0xffffffffu, sum0, 2, 4);
            sum1 += __shfl_xor_sync(0xffffffffu, sum1, 1, 4);
            sum1 += __shfl_xor_sync(0xffffffffu, sum1, 2, 4);
            l_r[mt][0] = l_r[mt][0] * a0 + sum0;
            l_r[mt][1] = l_r[mt][1] * a1 + sum1;
#pragma unroll
            for (int nf = 0; nf < 8; nf++) {
                o[mt][nf][0] *= a0; o[mt][nf][1] *= a0;
                o[mt][nf][2] *= a1; o[mt][nf][3] *= a1;
            }
#pragma unroll
            for (int nf = 0; nf < 8; nf++) {
                __half2 h0 = __floats2half2_rn(s[mt][nf][0], s[mt][nf][1]);
                __half2 h1 = __floats2half2_rn(s[mt][nf][2], s[mt][nf][3]);
                Pu[(mt * 16 + g) * KWD + nf * 4 + tg]     = *(uint32_t*)&h0;
                Pu[(mt * 16 + 8 + g) * KWD + nf * 4 + tg] = *(uint32_t*)&h1;
            }
        }
        __syncwarp();

        // ---- PV: P A-frags via ldmatrix.x4; V B-frags via ldmatrix.x4.trans ----
        const uint32_t pbase = sbase + (uint32_t)(H_P + w * 32 * KH) * 2;
#pragma unroll
        for (int ks = 0; ks < 4; ks++) {
            uint32_t pa[2][4];
#pragma unroll
            for (int mt = 0; mt < 2; mt++) {
                uint32_t addr = pbase +
                    (uint32_t)((mt * 16 + arow) * KH + ks * 16 + ak8) * 2;
                LDMX4(pa[mt][0], pa[mt][1], pa[mt][2], pa[mt][3], addr);
            }
#pragma unroll
            for (int nfp = 0; nfp < 4; nfp++) {
                int vrow = ks * 16 + (lane & 15);
                int vcol = nfp * 16 + (lane >> 4) * 8;
                uint32_t addr = vbase + (uint32_t)(vrow * KH + vcol) * 2;
                uint32_t v0, v1, v2, v3;
                LDMX4T(v0, v1, v2, v3, addr);
                uint32_t bA[2] = {v0, v1};
                uint32_t bB[2] = {v2, v3};
                MMA_F16(o[0][2 * nfp],     pa[0], bA);
                MMA_F16(o[1][2 * nfp],     pa[1], bA);
                MMA_F16(o[0][2 * nfp + 1], pa[0], bB);
                MMA_F16(o[1][2 * nfp + 1], pa[1], bB);
            }
        }
        __syncwarp();
        __syncthreads();
    }

    // ---- epilogue ----
#pragma unroll
    for (int mt = 0; mt < 2; mt++) {
        float i0 = 1.f / l_r[mt][0], i1 = 1.f / l_r[mt][1];
        float* op0 = out + ((size_t)b * SEQ + m0 + w * 32 + mt * 16 + g) * EMBED + h * HD;
        float* op1 = op0 + 8 * EMBED;
#pragma unroll
        for (int nf = 0; nf < 8; nf++) {
            float2 r0 = make_float2(o[mt][nf][0] * i0, o[mt][nf][1] * i0);
            float2 r1 = make_float2(o[mt][nf][2] * i1, o[mt][nf][3] * i1);
            *(float2*)(op0 + nf * 8 + 2 * tg) = r0;
            *(float2*)(op1 + nf * 8 + 2 * tg) = r1;
        }
    }
}

// ---------------------------------------------------------------------------
extern "C" void kernel_launch(void* const* d_in, const int* in_sizes, int n_in,
                              void* d_out, int out_size)
{
    const float* x    = (const float*)d_in[0];
    const float* W    = (const float*)d_in[1];
    const float* bias = (const float*)d_in[2];
    float* out = (float*)d_out;

    preround_kernel<<<2048, 256>>>((const float2*)x, (const float2*)W);

    cudaFuncSetAttribute(qkv_gemm_kernel, cudaFuncAttributeMaxDynamicSharedMemorySize,
                         (int)GEMM_SMEM);
    dim3 ggrid(THREE_E / 128, M_TOTAL / 128);
    qkv_gemm_kernel<<<ggrid, 256, GEMM_SMEM>>>(bias);

    cudaFuncSetAttribute(attn_kernel, cudaFuncAttributeMaxDynamicSharedMemorySize,
                         (int)ATTN_SMEM);
    dim3 agrid(SEQ / 128, HEADS, BATCH);
    attn_kernel<<<agrid, 128, ATTN_SMEM>>>(out);
}

// round 16
// speedup vs baseline: 27.0430x; 1.0279x over previous
#include <cuda_runtime.h>
#include <cuda_fp16.h>
#include <math.h>
#include <stdint.h>

#define EMBED   768
#define THREE_E 2304
#define HEADS   12
#define HD      64
#define BATCH   8
#define SEQ     1024
#define M_TOTAL (BATCH * SEQ)          // 8192
#define PER_BUF ((size_t)BATCH * HEADS * SEQ * HD)
#define LOG2E   1.44269504088896340736f

// Scratch: Q,K,V all [b][h][n][d] fp16 (Q pre-scaled by 0.125*log2e)
__device__ __half g_qkvh[3 * PER_BUF];
__device__ __half g_xh[(size_t)M_TOTAL * EMBED];
__device__ __half g_wh[(size_t)THREE_E * EMBED];

// ---- cp.async ----
__device__ __forceinline__ uint32_t smem_u32(const void* p) {
    return (uint32_t)__cvta_generic_to_shared(p);
}
__device__ __forceinline__ void cpa16(uint32_t s, const void* g) {
    asm volatile("cp.async.cg.shared.global [%0], [%1], 16;" :: "r"(s), "l"(g));
}
#define CPA_COMMIT() asm volatile("cp.async.commit_group;")
#define CPA_WAIT(n)  asm volatile("cp.async.wait_group %0;" :: "n"(n))

// ---- fp16 mma ----
#define MMA_F16(c, a, b) \
    asm volatile("mma.sync.aligned.m16n8k16.row.col.f32.f16.f16.f32 " \
        "{%0,%1,%2,%3},{%4,%5,%6,%7},{%8,%9},{%0,%1,%2,%3};" \
        : "+f"((c)[0]), "+f"((c)[1]), "+f"((c)[2]), "+f"((c)[3]) \
        : "r"((a)[0]), "r"((a)[1]), "r"((a)[2]), "r"((a)[3]), \
          "r"((b)[0]), "r"((b)[1]))

#define LDMX4(r0, r1, r2, r3, addr) \
    asm volatile("ldmatrix.sync.aligned.m8n8.x4.shared.b16 {%0,%1,%2,%3}, [%4];" \
        : "=r"(r0), "=r"(r1), "=r"(r2), "=r"(r3) : "r"(addr))
#define LDMX4T(r0, r1, r2, r3, addr) \
    asm volatile("ldmatrix.sync.aligned.m8n8.x4.trans.shared.b16 {%0,%1,%2,%3}, [%4];" \
        : "=r"(r0), "=r"(r1), "=r"(r2), "=r"(r3) : "r"(addr))

__device__ __forceinline__ float ex2f(float x) {
    float r; asm("ex2.approx.f32 %0, %1;" : "=f"(r) : "f"(x)); return r;
}
__device__ __forceinline__ uint32_t packh2(float a, float b) {
    __half2 h = __floats2half2_rn(a, b);
    return *(uint32_t*)&h;
}

// ---------------------------------------------------------------------------
// Kernel 0: convert X, W to fp16
// ---------------------------------------------------------------------------
#define XN2 ((size_t)M_TOTAL * EMBED / 2)
#define WN2 ((size_t)THREE_E * EMBED / 2)

__global__ __launch_bounds__(256) void preround_kernel(
    const float2* __restrict__ X, const float2* __restrict__ W)
{
    __half2* xh = (__half2*)g_xh;
    __half2* wh = (__half2*)g_wh;
    size_t i = (size_t)blockIdx.x * blockDim.x + threadIdx.x;
    size_t stride = (size_t)gridDim.x * blockDim.x;
    for (; i < XN2 + WN2; i += stride) {
        if (i < XN2) { float2 v = X[i]; xh[i] = __floats2half2_rn(v.x, v.y); }
        else { float2 v = W[i - XN2]; wh[i - XN2] = __floats2half2_rn(v.x, v.y); }
    }
}

// ---------------------------------------------------------------------------
// Kernel 1: QKV projection, fp16 mma GEMM, ldmatrix fragment loads.
// ---------------------------------------------------------------------------
#define AH 40
#define ABUF (128 * AH)
#define GEMM_SMEM (4 * ABUF * 2)       // 40960 B

__device__ __forceinline__ void qkv_scatter_h2(float v0, float v1, int m, int c) {
    int bidx = m >> 10;
    int n    = m & (SEQ - 1);
    int hh = c / 192;
    int r  = c - hh * 192;
    int which = r >> 6;
    int d = r & 63;
    if (which == 0) { v0 *= 0.125f * LOG2E; v1 *= 0.125f * LOG2E; }
    size_t idx = (size_t)which * PER_BUF +
                 (((size_t)bidx * HEADS + hh) * SEQ + n) * HD + d;
    *(__half2*)(g_qkvh + idx) = __floats2half2_rn(v0, v1);
}

__global__ __launch_bounds__(256, 2) void qkv_gemm_kernel(
    const float* __restrict__ bias)
{
    extern __shared__ __half gsm[];
    const uint32_t sb = smem_u32(gsm);

    const int tid  = threadIdx.x;
    const int lane = tid & 31;
    const int wid  = tid >> 5;
    const int wm   = wid >> 2;
    const int wn   = wid & 3;
    const int g    = lane >> 2;
    const int tg   = lane & 3;
    const int m0 = blockIdx.y * 128;
    const int n0 = blockIdx.x * 128;

    const int arow = (lane & 7) | (((lane >> 3) & 1) << 3);
    const int ak8  = ((lane >> 4) & 1) << 3;
    const int brow = ((lane >> 4) << 3) | (lane & 7);
    const int bk8  = ((lane >> 3) & 1) << 3;

    float acc[4][4][4];
#pragma unroll
    for (int mt = 0; mt < 4; mt++)
#pragma unroll
        for (int nt = 0; nt < 4; nt++)
#pragma unroll
            for (int k = 0; k < 4; k++) acc[mt][nt][k] = 0.f;

    {
#pragma unroll
        for (int it = 0; it < 2; it++) {
            int c = it * 256 + tid;
            int row = c >> 2, hc = (c & 3) * 8;
            cpa16(sb + (uint32_t)(row * AH + hc) * 2,
                  g_xh + (size_t)(m0 + row) * EMBED + hc);
            cpa16(sb + (uint32_t)(2 * ABUF + row * AH + hc) * 2,
                  g_wh + (size_t)(n0 + row) * EMBED + hc);
        }
        CPA_COMMIT();
    }

    for (int t = 0; t < EMBED / 32; t++) {
        if (t + 1 < EMBED / 32) {
            const int nb = (t + 1) & 1;
            const int k0 = (t + 1) * 32;
#pragma unroll
            for (int it = 0; it < 2; it++) {
                int c = it * 256 + tid;
                int row = c >> 2, hc = (c & 3) * 8;
                cpa16(sb + (uint32_t)(nb * ABUF + row * AH + hc) * 2,
                      g_xh + (size_t)(m0 + row) * EMBED + k0 + hc);
                cpa16(sb + (uint32_t)((2 + nb) * ABUF + row * AH + hc) * 2,
                      g_wh + (size_t)(n0 + row) * EMBED + k0 + hc);
            }
            CPA_COMMIT();
            CPA_WAIT(1);
        } else {
            CPA_WAIT(0);
        }
        __syncthreads();

        const uint32_t abase = sb + (uint32_t)((t & 1) * ABUF) * 2;
        const uint32_t bbase = sb + (uint32_t)((2 + (t & 1)) * ABUF) * 2;

#pragma unroll
        for (int ks = 0; ks < 2; ks++) {
            uint32_t af[4][4], bf[4][2];
#pragma unroll
            for (int mt = 0; mt < 4; mt++) {
                uint32_t addr = abase +
                    (uint32_t)((wm * 64 + mt * 16 + arow) * AH + ks * 16 + ak8) * 2;
                LDMX4(af[mt][0], af[mt][1], af[mt][2], af[mt][3], addr);
            }
#pragma unroll
            for (int p = 0; p < 2; p++) {
                uint32_t addr = bbase +
                    (uint32_t)((wn * 32 + p * 16 + brow) * AH + ks * 16 + bk8) * 2;
                uint32_t r0, r1, r2, r3;
                LDMX4(r0, r1, r2, r3, addr);
                bf[2 * p][0] = r0; bf[2 * p][1] = r1;
                bf[2 * p + 1][0] = r2; bf[2 * p + 1][1] = r3;
            }
#pragma unroll
            for (int mt = 0; mt < 4; mt++)
#pragma unroll
                for (int nt = 0; nt < 4; nt++)
                    MMA_F16(acc[mt][nt], af[mt], bf[nt]);
        }
        __syncthreads();
    }

#pragma unroll
    for (int mt = 0; mt < 4; mt++) {
#pragma unroll
        for (int nt = 0; nt < 4; nt++) {
            int row = m0 + wm * 64 + mt * 16 + g;
            int col = n0 + wn * 32 + nt * 8 + 2 * tg;
            float b0 = bias[col], b1 = bias[col + 1];
            qkv_scatter_h2(acc[mt][nt][0] + b0, acc[mt][nt][1] + b1, row,     col);
            qkv_scatter_h2(acc[mt][nt][2] + b0, acc[mt][nt][3] + b1, row + 8, col);
        }
    }
}

// ---------------------------------------------------------------------------
// Kernel 2: flash attention, fp16 mma, BN=64 tiles.
// P stays in registers: QK C-fragment layout == PV A-fragment layout.
// smem = K/V double buffers only (36,864 B).
// ---------------------------------------------------------------------------
#define KH   72
#define H_K0 0
#define H_K1 (64 * KH)
#define H_V0 (2 * 64 * KH)
#define H_V1 (3 * 64 * KH)
#define ATTN_SMEM (4 * 64 * KH * 2)    // 36864 B

__global__ __launch_bounds__(128, 2) void attn_kernel(float* __restrict__ out)
{
    extern __shared__ __half smh[];
    const uint32_t sbase = smem_u32(smh);

    const int b  = blockIdx.z;
    const int h  = blockIdx.y;
    const int m0 = blockIdx.x * 128;
    const size_t bh = (size_t)b * HEADS + h;
    const __half* Qh = g_qkvh + bh * SEQ * HD;
    const __half* Kh = g_qkvh + PER_BUF + bh * SEQ * HD;
    const __half* Vh = g_qkvh + 2 * PER_BUF + bh * SEQ * HD;

    const int tid  = threadIdx.x;
    const int lane = tid & 31;
    const int w    = tid >> 5;
    const int g    = lane >> 2;
    const int tg   = lane & 3;

    const int brow = ((lane >> 4) << 3) | (lane & 7);
    const int bk8  = ((lane >> 3) & 1) << 3;

    // ---- persistent Q fragments ----
    uint32_t qf[2][4][4];
    {
        const uint32_t* Qu = (const uint32_t*)Qh;
#pragma unroll
        for (int mt = 0; mt < 2; mt++) {
            const size_t r0 = (size_t)(m0 + w * 32 + mt * 16 + g) * (HD / 2);
#pragma unroll
            for (int ks = 0; ks < 4; ks++) {
                qf[mt][ks][0] = Qu[r0 + ks * 8 + tg];
                qf[mt][ks][1] = Qu[r0 + 8 * (HD / 2) + ks * 8 + tg];
                qf[mt][ks][2] = Qu[r0 + ks * 8 + tg + 4];
                qf[mt][ks][3] = Qu[r0 + 8 * (HD / 2) + ks * 8 + tg + 4];
            }
        }
    }

    // ---- stage KV tile 0 ----
#pragma unroll
    for (int it = 0; it < 4; it++) {
        int c = it * 128 + tid;
        int row = c >> 3, hc = (c & 7) * 8;
        cpa16(sbase + (uint32_t)(H_K0 + row * KH + hc) * 2,
              Kh + (size_t)row * HD + hc);
        cpa16(sbase + (uint32_t)(H_V0 + row * KH + hc) * 2,
              Vh + (size_t)row * HD + hc);
    }
    CPA_COMMIT();

    float o[2][8][4];
#pragma unroll
    for (int mt = 0; mt < 2; mt++)
#pragma unroll
        for (int nf = 0; nf < 8; nf++)
#pragma unroll
            for (int k = 0; k < 4; k++) o[mt][nf][k] = 0.f;
    float m_r[2][2], l_r[2][2];
#pragma unroll
    for (int mt = 0; mt < 2; mt++) {
        m_r[mt][0] = m_r[mt][1] = -1e30f;
        l_r[mt][0] = l_r[mt][1] = 0.f;
    }

    for (int t = 0; t < SEQ / 64; t++) {
        const int buf = t & 1;
        if (t + 1 < SEQ / 64) {
            const int n1 = (t + 1) * 64;
            const uint32_t kd = buf ? H_K0 : H_K1;
            const uint32_t vd = buf ? H_V0 : H_V1;
#pragma unroll
            for (int it = 0; it < 4; it++) {
                int c = it * 128 + tid;
                int row = c >> 3, hc = (c & 7) * 8;
                cpa16(sbase + (kd + (uint32_t)(row * KH + hc)) * 2,
                      Kh + (size_t)(n1 + row) * HD + hc);
                cpa16(sbase + (vd + (uint32_t)(row * KH + hc)) * 2,
                      Vh + (size_t)(n1 + row) * HD + hc);
            }
            CPA_COMMIT();
            CPA_WAIT(1);
        } else {
            CPA_WAIT(0);
        }
        __syncthreads();

        const uint32_t kbase = sbase + (uint32_t)(buf ? H_K1 : H_K0) * 2;
        const uint32_t vbase = sbase + (uint32_t)(buf ? H_V1 : H_V0) * 2;

        // ---- QK: S (2x 16q x 64j); K B-frags via ldmatrix.x4 ----
        float s[2][8][4];
#pragma unroll
        for (int mt = 0; mt < 2; mt++)
#pragma unroll
            for (int nf = 0; nf < 8; nf++)
#pragma unroll
                for (int k = 0; k < 4; k++) s[mt][nf][k] = 0.f;
#pragma unroll
        for (int ks = 0; ks < 4; ks++) {
#pragma unroll
            for (int p = 0; p < 4; p++) {
                uint32_t addr = kbase +
                    (uint32_t)((p * 16 + brow) * KH + ks * 16 + bk8) * 2;
                uint32_t r0, r1, r2, r3;
                LDMX4(r0, r1, r2, r3, addr);
                uint32_t bA[2] = {r0, r1};
                uint32_t bB[2] = {r2, r3};
                MMA_F16(s[0][2 * p],     qf[0][ks], bA);
                MMA_F16(s[1][2 * p],     qf[1][ks], bA);
                MMA_F16(s[0][2 * p + 1], qf[0][ks], bB);
                MMA_F16(s[1][2 * p + 1], qf[1][ks], bB);
            }
        }

        // ---- online softmax; pack P into registers (A-frag layout) ----
        uint32_t phA[2][8], phB[2][8];
#pragma unroll
        for (int mt = 0; mt < 2; mt++) {
            float mx0 = -1e30f, mx1 = -1e30f;
#pragma unroll
            for (int nf = 0; nf < 8; nf++) {
                mx0 = fmaxf(mx0, fmaxf(s[mt][nf][0], s[mt][nf][1]));
                mx1 = fmaxf(mx1, fmaxf(s[mt][nf][2], s[mt][nf][3]));
            }
            mx0 = fmaxf(mx0, __shfl_xor_sync(0xffffffffu, mx0, 1, 4));
            mx0 = fmaxf(mx0, __shfl_xor_sync(0xffffffffu, mx0, 2, 4));
            mx1 = fmaxf(mx1, __shfl_xor_sync(0xffffffffu, mx1, 1, 4));
            mx1 = fmaxf(mx1, __shfl_xor_sync(0xffffffffu, mx1, 2, 4));
            float mn0 = fmaxf(m_r[mt][0], mx0), mn1 = fmaxf(m_r[mt][1], mx1);
            float a0 = ex2f(m_r[mt][0] - mn0), a1 = ex2f(m_r[mt][1] - mn1);
            m_r[mt][0] = mn0; m_r[mt][1] = mn1;
            float sum0 = 0.f, sum1 = 0.f;
#pragma unroll
            for (int nf = 0; nf < 8; nf++) {
                s[mt][nf][0] = ex2f(s[mt][nf][0] - mn0);
                s[mt][nf][1] = ex2f(s[mt][nf][1] - mn0);
                s[mt][nf][2] = ex2f(s[mt][nf][2] - mn1);
                s[mt][nf][3] = ex2f(s[mt][nf][3] - mn1);
                sum0 += s[mt][nf][0] + s[mt][nf][1];
                sum1 += s[mt][nf][2] + s[mt][nf][3];
                phA[mt][nf] = packh2(s[mt][nf][0], s[mt][nf][1]);
                phB[mt][nf] = packh2(s[mt][nf][2], s[mt][nf][3]);
            }
            sum0 += __shfl_xor_sync(0xffffffffu, sum0, 1, 4);
            sum0 += __shfl_xor_sync(0xffffffffu, sum0, 2, 4);
            sum1 += __shfl_xor_sync(0xffffffffu, sum1, 1, 4);
            sum1 += __shfl_xor_sync(0xffffffffu, sum1, 2, 4);
            l_r[mt][0] = l_r[mt][0] * a0 + sum0;
            l_r[mt][1] = l_r[mt][1] * a1 + sum1;
#pragma unroll
            for (int nf = 0; nf < 8; nf++) {
                o[mt][nf][0] *= a0; o[mt][nf][1] *= a0;
                o[mt][nf][2] *= a1; o[mt][nf][3] *= a1;
            }
        }

        // ---- PV: P A-frags straight from registers; V via ldmatrix.x4.trans ----
#pragma unroll
        for (int ks = 0; ks < 4; ks++) {
            uint32_t pa[2][4];
#pragma unroll
            for (int mt = 0; mt < 2; mt++) {
                pa[mt][0] = phA[mt][2 * ks];
                pa[mt][1] = phB[mt][2 * ks];
                pa[mt][2] = phA[mt][2 * ks + 1];
                pa[mt][3] = phB[mt][2 * ks + 1];
            }
#pragma unroll
            for (int nfp = 0; nfp < 4; nfp++) {
                int vrow = ks * 16 + (lane & 15);
                int vcol = nfp * 16 + (lane >> 4) * 8;
                uint32_t addr = vbase + (uint32_t)(vrow * KH + vcol) * 2;
                uint32_t v0, v1, v2, v3;
                LDMX4T(v0, v1, v2, v3, addr);
                uint32_t bA[2] = {v0, v1};
                uint32_t bB[2] = {v2, v3};
                MMA_F16(o[0][2 * nfp],     pa[0], bA);
                MMA_F16(o[1][2 * nfp],     pa[1], bA);
                MMA_F16(o[0][2 * nfp + 1], pa[0], bB);
                MMA_F16(o[1][2 * nfp + 1], pa[1], bB);
            }
        }
        __syncthreads();
    }

    // ---- epilogue ----
#pragma unroll
    for (int mt = 0; mt < 2; mt++) {
        float i0 = 1.f / l_r[mt][0], i1 = 1.f / l_r[mt][1];
        float* op0 = out + ((size_t)b * SEQ + m0 + w * 32 + mt * 16 + g) * EMBED + h * HD;
        float* op1 = op0 + 8 * EMBED;
#pragma unroll
        for (int nf = 0; nf < 8; nf++) {
            float2 r0 = make_float2(o[mt][nf][0] * i0, o[mt][nf][1] * i0);
            float2 r1 = make_float2(o[mt][nf][2] * i1, o[mt][nf][3] * i1);
            *(float2*)(op0 + nf * 8 + 2 * tg) = r0;
            *(float2*)(op1 + nf * 8 + 2 * tg) = r1;
        }
    }
}

// ---------------------------------------------------------------------------
extern "C" void kernel_launch(void* const* d_in, const int* in_sizes, int n_in,
                              void* d_out, int out_size)
{
    const float* x    = (const float*)d_in[0];
    const float* W    = (const float*)d_in[1];
    const float* bias = (const float*)d_in[2];
    float* out = (float*)d_out;

    preround_kernel<<<2048, 256>>>((const float2*)x, (const float2*)W);

    cudaFuncSetAttribute(qkv_gemm_kernel, cudaFuncAttributeMaxDynamicSharedMemorySize,
                         (int)GEMM_SMEM);
    dim3 ggrid(THREE_E / 128, M_TOTAL / 128);
    qkv_gemm_kernel<<<ggrid, 256, GEMM_SMEM>>>(bias);

    cudaFuncSetAttribute(attn_kernel, cudaFuncAttributeMaxDynamicSharedMemorySize,
                         (int)ATTN_SMEM);
    dim3 agrid(SEQ / 128, HEADS, BATCH);
    attn_kernel<<<agrid, 128, ATTN_SMEM>>>(out);
}

// round 17
// speedup vs baseline: 27.9993x; 1.0354x over previous
#include <cuda_runtime.h>
#include <cuda_fp16.h>
#include <math.h>
#include <stdint.h>

#define EMBED   768
#define THREE_E 2304
#define HEADS   12
#define HD      64
#define BATCH   8
#define SEQ     1024
#define M_TOTAL (BATCH * SEQ)          // 8192
#define PER_BUF ((size_t)BATCH * HEADS * SEQ * HD)
#define LOG2E   1.44269504088896340736f

// Scratch: Q,K,V all [b][h][n][d] fp16 (Q pre-scaled by 0.125*log2e)
__device__ __half g_qkvh[3 * PER_BUF];
__device__ __half g_xh[(size_t)M_TOTAL * EMBED];
__device__ __half g_wh[(size_t)THREE_E * EMBED];

// ---- cp.async ----
__device__ __forceinline__ uint32_t smem_u32(const void* p) {
    return (uint32_t)__cvta_generic_to_shared(p);
}
__device__ __forceinline__ void cpa16(uint32_t s, const void* g) {
    asm volatile("cp.async.cg.shared.global [%0], [%1], 16;" :: "r"(s), "l"(g));
}
#define CPA_COMMIT() asm volatile("cp.async.commit_group;")
#define CPA_WAIT(n)  asm volatile("cp.async.wait_group %0;" :: "n"(n))

// ---- fp16 mma ----
#define MMA_F16(c, a, b) \
    asm volatile("mma.sync.aligned.m16n8k16.row.col.f32.f16.f16.f32 " \
        "{%0,%1,%2,%3},{%4,%5,%6,%7},{%8,%9},{%0,%1,%2,%3};" \
        : "+f"((c)[0]), "+f"((c)[1]), "+f"((c)[2]), "+f"((c)[3]) \
        : "r"((a)[0]), "r"((a)[1]), "r"((a)[2]), "r"((a)[3]), \
          "r"((b)[0]), "r"((b)[1]))

#define LDMX4(r0, r1, r2, r3, addr) \
    asm volatile("ldmatrix.sync.aligned.m8n8.x4.shared.b16 {%0,%1,%2,%3}, [%4];" \
        : "=r"(r0), "=r"(r1), "=r"(r2), "=r"(r3) : "r"(addr))
#define LDMX4T(r0, r1, r2, r3, addr) \
    asm volatile("ldmatrix.sync.aligned.m8n8.x4.trans.shared.b16 {%0,%1,%2,%3}, [%4];" \
        : "=r"(r0), "=r"(r1), "=r"(r2), "=r"(r3) : "r"(addr))

__device__ __forceinline__ float ex2f(float x) {
    float r; asm("ex2.approx.f32 %0, %1;" : "=f"(r) : "f"(x)); return r;
}
__device__ __forceinline__ uint32_t packh2(float a, float b) {
    __half2 h = __floats2half2_rn(a, b);
    return *(uint32_t*)&h;
}
// dual-half exp2: one MUFU for two softmax weights, output already P-packed
#define EX2H2(d, x) asm("ex2.approx.f16x2 %0, %1;" : "=r"(d) : "r"(x))

// ---------------------------------------------------------------------------
// Kernel 0: convert X, W to fp16
// ---------------------------------------------------------------------------
#define XN2 ((size_t)M_TOTAL * EMBED / 2)
#define WN2 ((size_t)THREE_E * EMBED / 2)

__global__ __launch_bounds__(256) void preround_kernel(
    const float2* __restrict__ X, const float2* __restrict__ W)
{
    __half2* xh = (__half2*)g_xh;
    __half2* wh = (__half2*)g_wh;
    size_t i = (size_t)blockIdx.x * blockDim.x + threadIdx.x;
    size_t stride = (size_t)gridDim.x * blockDim.x;
    for (; i < XN2 + WN2; i += stride) {
        if (i < XN2) { float2 v = X[i]; xh[i] = __floats2half2_rn(v.x, v.y); }
        else { float2 v = W[i - XN2]; wh[i - XN2] = __floats2half2_rn(v.x, v.y); }
    }
}

// ---------------------------------------------------------------------------
// Kernel 1: QKV projection, fp16 mma GEMM, ldmatrix fragment loads.
// ---------------------------------------------------------------------------
#define AH 40
#define ABUF (128 * AH)
#define GEMM_SMEM (4 * ABUF * 2)       // 40960 B

__device__ __forceinline__ void qkv_scatter_h2(float v0, float v1, int m, int c) {
    int bidx = m >> 10;
    int n    = m & (SEQ - 1);
    int hh = c / 192;
    int r  = c - hh * 192;
    int which = r >> 6;
    int d = r & 63;
    if (which == 0) { v0 *= 0.125f * LOG2E; v1 *= 0.125f * LOG2E; }
    size_t idx = (size_t)which * PER_BUF +
                 (((size_t)bidx * HEADS + hh) * SEQ + n) * HD + d;
    *(__half2*)(g_qkvh + idx) = __floats2half2_rn(v0, v1);
}

__global__ __launch_bounds__(256, 2) void qkv_gemm_kernel(
    const float* __restrict__ bias)
{
    extern __shared__ __half gsm[];
    const uint32_t sb = smem_u32(gsm);

    const int tid  = threadIdx.x;
    const int lane = tid & 31;
    const int wid  = tid >> 5;
    const int wm   = wid >> 2;
    const int wn   = wid & 3;
    const int g    = lane >> 2;
    const int tg   = lane & 3;
    const int m0 = blockIdx.y * 128;
    const int n0 = blockIdx.x * 128;

    const int arow = (lane & 7) | (((lane >> 3) & 1) << 3);
    const int ak8  = ((lane >> 4) & 1) << 3;
    const int brow = ((lane >> 4) << 3) | (lane & 7);
    const int bk8  = ((lane >> 3) & 1) << 3;

    float acc[4][4][4];
#pragma unroll
    for (int mt = 0; mt < 4; mt++)
#pragma unroll
        for (int nt = 0; nt < 4; nt++)
#pragma unroll
            for (int k = 0; k < 4; k++) acc[mt][nt][k] = 0.f;

    {
#pragma unroll
        for (int it = 0; it < 2; it++) {
            int c = it * 256 + tid;
            int row = c >> 2, hc = (c & 3) * 8;
            cpa16(sb + (uint32_t)(row * AH + hc) * 2,
                  g_xh + (size_t)(m0 + row) * EMBED + hc);
            cpa16(sb + (uint32_t)(2 * ABUF + row * AH + hc) * 2,
                  g_wh + (size_t)(n0 + row) * EMBED + hc);
        }
        CPA_COMMIT();
    }

    for (int t = 0; t < EMBED / 32; t++) {
        if (t + 1 < EMBED / 32) {
            const int nb = (t + 1) & 1;
            const int k0 = (t + 1) * 32;
#pragma unroll
            for (int it = 0; it < 2; it++) {
                int c = it * 256 + tid;
                int row = c >> 2, hc = (c & 3) * 8;
                cpa16(sb + (uint32_t)(nb * ABUF + row * AH + hc) * 2,
                      g_xh + (size_t)(m0 + row) * EMBED + k0 + hc);
                cpa16(sb + (uint32_t)((2 + nb) * ABUF + row * AH + hc) * 2,
                      g_wh + (size_t)(n0 + row) * EMBED + k0 + hc);
            }
            CPA_COMMIT();
            CPA_WAIT(1);
        } else {
            CPA_WAIT(0);
        }
        __syncthreads();

        const uint32_t abase = sb + (uint32_t)((t & 1) * ABUF) * 2;
        const uint32_t bbase = sb + (uint32_t)((2 + (t & 1)) * ABUF) * 2;

#pragma unroll
        for (int ks = 0; ks < 2; ks++) {
            uint32_t af[4][4], bf[4][2];
#pragma unroll
            for (int mt = 0; mt < 4; mt++) {
                uint32_t addr = abase +
                    (uint32_t)((wm * 64 + mt * 16 + arow) * AH + ks * 16 + ak8) * 2;
                LDMX4(af[mt][0], af[mt][1], af[mt][2], af[mt][3], addr);
            }
#pragma unroll
            for (int p = 0; p < 2; p++) {
                uint32_t addr = bbase +
                    (uint32_t)((wn * 32 + p * 16 + brow) * AH + ks * 16 + bk8) * 2;
                uint32_t r0, r1, r2, r3;
                LDMX4(r0, r1, r2, r3, addr);
                bf[2 * p][0] = r0; bf[2 * p][1] = r1;
                bf[2 * p + 1][0] = r2; bf[2 * p + 1][1] = r3;
            }
#pragma unroll
            for (int mt = 0; mt < 4; mt++)
#pragma unroll
                for (int nt = 0; nt < 4; nt++)
                    MMA_F16(acc[mt][nt], af[mt], bf[nt]);
        }
        __syncthreads();
    }

#pragma unroll
    for (int mt = 0; mt < 4; mt++) {
#pragma unroll
        for (int nt = 0; nt < 4; nt++) {
            int row = m0 + wm * 64 + mt * 16 + g;
            int col = n0 + wn * 32 + nt * 8 + 2 * tg;
            float b0 = bias[col], b1 = bias[col + 1];
            qkv_scatter_h2(acc[mt][nt][0] + b0, acc[mt][nt][1] + b1, row,     col);
            qkv_scatter_h2(acc[mt][nt][2] + b0, acc[mt][nt][3] + b1, row + 8, col);
        }
    }
}

// ---------------------------------------------------------------------------
// Kernel 2: flash attention, fp16 mma, BN=64 tiles.
// P in registers (QK C-frag == PV A-frag); softmax ex2 in f16x2 (half MUFU);
// row-sum l computed by mma against a ones-column (no fp32 sum reduction).
// ---------------------------------------------------------------------------
#define KH   72
#define H_K0 0
#define H_K1 (64 * KH)
#define H_V0 (2 * 64 * KH)
#define H_V1 (3 * 64 * KH)
#define ATTN_SMEM (4 * 64 * KH * 2)    // 36864 B
#define ONES_H2 0x3C003C00u            // (1.0h, 1.0h)

__global__ __launch_bounds__(128, 2) void attn_kernel(float* __restrict__ out)
{
    extern __shared__ __half smh[];
    const uint32_t sbase = smem_u32(smh);

    const int b  = blockIdx.z;
    const int h  = blockIdx.y;
    const int m0 = blockIdx.x * 128;
    const size_t bh = (size_t)b * HEADS + h;
    const __half* Qh = g_qkvh + bh * SEQ * HD;
    const __half* Kh = g_qkvh + PER_BUF + bh * SEQ * HD;
    const __half* Vh = g_qkvh + 2 * PER_BUF + bh * SEQ * HD;

    const int tid  = threadIdx.x;
    const int lane = tid & 31;
    const int w    = tid >> 5;
    const int g    = lane >> 2;
    const int tg   = lane & 3;

    const int brow = ((lane >> 4) << 3) | (lane & 7);
    const int bk8  = ((lane >> 3) & 1) << 3;

    // ---- persistent Q fragments ----
    uint32_t qf[2][4][4];
    {
        const uint32_t* Qu = (const uint32_t*)Qh;
#pragma unroll
        for (int mt = 0; mt < 2; mt++) {
            const size_t r0 = (size_t)(m0 + w * 32 + mt * 16 + g) * (HD / 2);
#pragma unroll
            for (int ks = 0; ks < 4; ks++) {
                qf[mt][ks][0] = Qu[r0 + ks * 8 + tg];
                qf[mt][ks][1] = Qu[r0 + 8 * (HD / 2) + ks * 8 + tg];
                qf[mt][ks][2] = Qu[r0 + ks * 8 + tg + 4];
                qf[mt][ks][3] = Qu[r0 + 8 * (HD / 2) + ks * 8 + tg + 4];
            }
        }
    }

    // ---- stage KV tile 0 ----
#pragma unroll
    for (int it = 0; it < 4; it++) {
        int c = it * 128 + tid;
        int row = c >> 3, hc = (c & 7) * 8;
        cpa16(sbase + (uint32_t)(H_K0 + row * KH + hc) * 2,
              Kh + (size_t)row * HD + hc);
        cpa16(sbase + (uint32_t)(H_V0 + row * KH + hc) * 2,
              Vh + (size_t)row * HD + hc);
    }
    CPA_COMMIT();

    float o[2][8][4];
#pragma unroll
    for (int mt = 0; mt < 2; mt++)
#pragma unroll
        for (int nf = 0; nf < 8; nf++)
#pragma unroll
            for (int k = 0; k < 4; k++) o[mt][nf][k] = 0.f;
    float lacc[2][4];                  // l via P . ones  (c0: row g, c2: row g+8)
#pragma unroll
    for (int mt = 0; mt < 2; mt++)
#pragma unroll
        for (int k = 0; k < 4; k++) lacc[mt][k] = 0.f;
    float m_r[2][2];
#pragma unroll
    for (int mt = 0; mt < 2; mt++) { m_r[mt][0] = m_r[mt][1] = -1e30f; }

    const uint32_t bones[2] = {ONES_H2, ONES_H2};

    for (int t = 0; t < SEQ / 64; t++) {
        const int buf = t & 1;
        if (t + 1 < SEQ / 64) {
            const int n1 = (t + 1) * 64;
            const uint32_t kd = buf ? H_K0 : H_K1;
            const uint32_t vd = buf ? H_V0 : H_V1;
#pragma unroll
            for (int it = 0; it < 4; it++) {
                int c = it * 128 + tid;
                int row = c >> 3, hc = (c & 7) * 8;
                cpa16(sbase + (kd + (uint32_t)(row * KH + hc)) * 2,
                      Kh + (size_t)(n1 + row) * HD + hc);
                cpa16(sbase + (vd + (uint32_t)(row * KH + hc)) * 2,
                      Vh + (size_t)(n1 + row) * HD + hc);
            }
            CPA_COMMIT();
            CPA_WAIT(1);
        } else {
            CPA_WAIT(0);
        }
        __syncthreads();

        const uint32_t kbase = sbase + (uint32_t)(buf ? H_K1 : H_K0) * 2;
        const uint32_t vbase = sbase + (uint32_t)(buf ? H_V1 : H_V0) * 2;

        // ---- QK: S (2x 16q x 64j); K B-frags via ldmatrix.x4 ----
        float s[2][8][4];
#pragma unroll
        for (int mt = 0; mt < 2; mt++)
#pragma unroll
            for (int nf = 0; nf < 8; nf++)
#pragma unroll
                for (int k = 0; k < 4; k++) s[mt][nf][k] = 0.f;
#pragma unroll
        for (int ks = 0; ks < 4; ks++) {
#pragma unroll
            for (int p = 0; p < 4; p++) {
                uint32_t addr = kbase +
                    (uint32_t)((p * 16 + brow) * KH + ks * 16 + bk8) * 2;
                uint32_t r0, r1, r2, r3;
                LDMX4(r0, r1, r2, r3, addr);
                uint32_t bA[2] = {r0, r1};
                uint32_t bB[2] = {r2, r3};
                MMA_F16(s[0][2 * p],     qf[0][ks], bA);
                MMA_F16(s[1][2 * p],     qf[1][ks], bA);
                MMA_F16(s[0][2 * p + 1], qf[0][ks], bB);
                MMA_F16(s[1][2 * p + 1], qf[1][ks], bB);
            }
        }

        // ---- online softmax: max (fp32) -> dual-half ex2 -> P fragments ----
        uint32_t phA[2][8], phB[2][8];
#pragma unroll
        for (int mt = 0; mt < 2; mt++) {
            float mx0 = -1e30f, mx1 = -1e30f;
#pragma unroll
            for (int nf = 0; nf < 8; nf++) {
                mx0 = fmaxf(mx0, fmaxf(s[mt][nf][0], s[mt][nf][1]));
                mx1 = fmaxf(mx1, fmaxf(s[mt][nf][2], s[mt][nf][3]));
            }
            mx0 = fmaxf(mx0, __shfl_xor_sync(0xffffffffu, mx0, 1, 4));
            mx0 = fmaxf(mx0, __shfl_xor_sync(0xffffffffu, mx0, 2, 4));
            mx1 = fmaxf(mx1, __shfl_xor_sync(0xffffffffu, mx1, 1, 4));
            mx1 = fmaxf(mx1, __shfl_xor_sync(0xffffffffu, mx1, 2, 4));
            float mn0 = fmaxf(m_r[mt][0], mx0), mn1 = fmaxf(m_r[mt][1], mx1);
            float a0 = ex2f(m_r[mt][0] - mn0), a1 = ex2f(m_r[mt][1] - mn1);
            m_r[mt][0] = mn0; m_r[mt][1] = mn1;
#pragma unroll
            for (int nf = 0; nf < 8; nf++) {
                uint32_t d0 = packh2(s[mt][nf][0] - mn0, s[mt][nf][1] - mn0);
                uint32_t d1 = packh2(s[mt][nf][2] - mn1, s[mt][nf][3] - mn1);
                EX2H2(phA[mt][nf], d0);
                EX2H2(phB[mt][nf], d1);
            }
            // rescale O and L accumulators
#pragma unroll
            for (int nf = 0; nf < 8; nf++) {
                o[mt][nf][0] *= a0; o[mt][nf][1] *= a0;
                o[mt][nf][2] *= a1; o[mt][nf][3] *= a1;
            }
            lacc[mt][0] *= a0; lacc[mt][1] *= a0;
            lacc[mt][2] *= a1; lacc[mt][3] *= a1;
        }

        // ---- PV: P A-frags from registers; V via ldmatrix.x4.trans;
        //      l accumulated with an extra mma against ones ----
#pragma unroll
        for (int ks = 0; ks < 4; ks++) {
            uint32_t pa[2][4];
#pragma unroll
            for (int mt = 0; mt < 2; mt++) {
                pa[mt][0] = phA[mt][2 * ks];
                pa[mt][1] = phB[mt][2 * ks];
                pa[mt][2] = phA[mt][2 * ks + 1];
                pa[mt][3] = phB[mt][2 * ks + 1];
            }
            MMA_F16(lacc[0], pa[0], bones);
            MMA_F16(lacc[1], pa[1], bones);
#pragma unroll
            for (int nfp = 0; nfp < 4; nfp++) {
                int vrow = ks * 16 + (lane & 15);
                int vcol = nfp * 16 + (lane >> 4) * 8;
                uint32_t addr = vbase + (uint32_t)(vrow * KH + vcol) * 2;
                uint32_t v0, v1, v2, v3;
                LDMX4T(v0, v1, v2, v3, addr);
                uint32_t bA[2] = {v0, v1};
                uint32_t bB[2] = {v2, v3};
                MMA_F16(o[0][2 * nfp],     pa[0], bA);
                MMA_F16(o[1][2 * nfp],     pa[1], bA);
                MMA_F16(o[0][2 * nfp + 1], pa[0], bB);
                MMA_F16(o[1][2 * nfp + 1], pa[1], bB);
            }
        }
        __syncthreads();
    }

    // ---- epilogue ----
#pragma unroll
    for (int mt = 0; mt < 2; mt++) {
        float i0 = 1.f / lacc[mt][0], i1 = 1.f / lacc[mt][2];
        float* op0 = out + ((size_t)b * SEQ + m0 + w * 32 + mt * 16 + g) * EMBED + h * HD;
        float* op1 = op0 + 8 * EMBED;
#pragma unroll
        for (int nf = 0; nf < 8; nf++) {
            float2 r0 = make_float2(o[mt][nf][0] * i0, o[mt][nf][1] * i0);
            float2 r1 = make_float2(o[mt][nf][2] * i1, o[mt][nf][3] * i1);
            *(float2*)(op0 + nf * 8 + 2 * tg) = r0;
            *(float2*)(op1 + nf * 8 + 2 * tg) = r1;
        }
    }
}

// ---------------------------------------------------------------------------
extern "C" void kernel_launch(void* const* d_in, const int* in_sizes, int n_in,
                              void* d_out, int out_size)
{
    const float* x    = (const float*)d_in[0];
    const float* W    = (const float*)d_in[1];
    const float* bias = (const float*)d_in[2];
    float* out = (float*)d_out;

    preround_kernel<<<2048, 256>>>((const float2*)x, (const float2*)W);

    cudaFuncSetAttribute(qkv_gemm_kernel, cudaFuncAttributeMaxDynamicSharedMemorySize,
                         (int)GEMM_SMEM);
    dim3 ggrid(THREE_E / 128, M_TOTAL / 128);
    qkv_gemm_kernel<<<ggrid, 256, GEMM_SMEM>>>(bias);

    cudaFuncSetAttribute(attn_kernel, cudaFuncAttributeMaxDynamicSharedMemorySize,
                         (int)ATTN_SMEM);
    dim3 agrid(SEQ / 128, HEADS, BATCH);
    attn_kernel<<<agrid, 128, ATTN_SMEM>>>(out);
}